// round 1
// baseline (speedup 1.0000x reference)
#include <cuda_runtime.h>
#include <math.h>

#define SEQ 4096
#define DIM 1024

// Static device scratch (allowed; no dynamic allocation anywhere).
__device__ float g_Q[SEQ * DIM];
__device__ float g_K[SEQ * DIM];
__device__ float g_V[SEQ * DIM];
__device__ float g_S[(size_t)SEQ * SEQ];

// ---------------------------------------------------------------------------
// SGEMM: C[M,N] = alpha * A[M,K] * op(B)
//   TB=false: B is [K,N] row-major (NN)
//   TB=true : B is [N,K] row-major (NT, i.e. C = A * B^T)
// Tiles: 64x64x16, 256 threads, 4x4 per-thread micro-tile.
// All dims assumed divisible by 64/16 (true here: 4096, 1024).
// ---------------------------------------------------------------------------
template <bool TB>
__global__ __launch_bounds__(256) void sgemm64(
    const float* __restrict__ A, const float* __restrict__ B,
    float* __restrict__ C, int M, int N, int Kdim,
    int lda, int ldb, int ldc, float alpha)
{
    __shared__ float As[16][64];   // As[k][m]
    __shared__ float Bs[16][64];   // Bs[k][n]

    const int tid = threadIdx.x;
    const int tx = tid & 15;       // 0..15 -> 4 cols each
    const int ty = tid >> 4;       // 0..15 -> 4 rows each

    const int row0 = blockIdx.y * 64;
    const int col0 = blockIdx.x * 64;

    // A tile load mapping: 64 rows x 16 cols = 256 float4
    const int ar = tid >> 2;           // 0..63 (tile row)
    const int ac = (tid & 3) * 4;      // 0,4,8,12 (tile col)

    // B tile (NN): 16 rows x 64 cols
    const int br = tid >> 4;           // 0..15 (k)
    const int bc = (tid & 15) * 4;     // 0..60 (n)

    // B tile (NT): 64 rows (n) x 16 cols (k)
    const int tr = tid >> 2;           // 0..63 (n)
    const int tc = (tid & 3) * 4;      // 0,4,8,12 (k)

    float acc[4][4];
#pragma unroll
    for (int i = 0; i < 4; i++)
#pragma unroll
        for (int j = 0; j < 4; j++) acc[i][j] = 0.0f;

    for (int k0 = 0; k0 < Kdim; k0 += 16) {
        // load A tile (store transposed: As[k][m])
        {
            float4 a = *reinterpret_cast<const float4*>(&A[(size_t)(row0 + ar) * lda + k0 + ac]);
            As[ac + 0][ar] = a.x;
            As[ac + 1][ar] = a.y;
            As[ac + 2][ar] = a.z;
            As[ac + 3][ar] = a.w;
        }
        // load B tile
        if (!TB) {
            float4 b = *reinterpret_cast<const float4*>(&B[(size_t)(k0 + br) * ldb + col0 + bc]);
            *reinterpret_cast<float4*>(&Bs[br][bc]) = b;
        } else {
            float4 b = *reinterpret_cast<const float4*>(&B[(size_t)(col0 + tr) * ldb + k0 + tc]);
            Bs[tc + 0][tr] = b.x;
            Bs[tc + 1][tr] = b.y;
            Bs[tc + 2][tr] = b.z;
            Bs[tc + 3][tr] = b.w;
        }
        __syncthreads();

#pragma unroll
        for (int k = 0; k < 16; k++) {
            float4 a = *reinterpret_cast<const float4*>(&As[k][ty * 4]);
            float4 b = *reinterpret_cast<const float4*>(&Bs[k][tx * 4]);
            float av[4] = {a.x, a.y, a.z, a.w};
            float bv[4] = {b.x, b.y, b.z, b.w};
#pragma unroll
            for (int i = 0; i < 4; i++)
#pragma unroll
                for (int j = 0; j < 4; j++)
                    acc[i][j] = fmaf(av[i], bv[j], acc[i][j]);
        }
        __syncthreads();
    }

#pragma unroll
    for (int i = 0; i < 4; i++) {
        float4 o;
        o.x = alpha * acc[i][0];
        o.y = alpha * acc[i][1];
        o.z = alpha * acc[i][2];
        o.w = alpha * acc[i][3];
        *reinterpret_cast<float4*>(&C[(size_t)(row0 + ty * 4 + i) * ldc + col0 + tx * 4]) = o;
    }
}

// ---------------------------------------------------------------------------
// Row softmax over S[SEQ, SEQ], one block per row.
// ---------------------------------------------------------------------------
__global__ __launch_bounds__(256) void softmax_rows(float* __restrict__ S, int N)
{
    const int row = blockIdx.x;
    float* p = S + (size_t)row * N;
    const int tid = threadIdx.x;
    __shared__ float red[256];

    // 1) row max
    float mx = -INFINITY;
    for (int i = tid; i < N; i += 256) mx = fmaxf(mx, p[i]);
    red[tid] = mx;
    __syncthreads();
#pragma unroll
    for (int s = 128; s > 0; s >>= 1) {
        if (tid < s) red[tid] = fmaxf(red[tid], red[tid + s]);
        __syncthreads();
    }
    mx = red[0];
    __syncthreads();

    // 2) exp and sum
    float sum = 0.0f;
    for (int i = tid; i < N; i += 256) {
        float e = expf(p[i] - mx);
        p[i] = e;
        sum += e;
    }
    red[tid] = sum;
    __syncthreads();
#pragma unroll
    for (int s = 128; s > 0; s >>= 1) {
        if (tid < s) red[tid] += red[tid + s];
        __syncthreads();
    }
    const float inv = 1.0f / red[0];
    __syncthreads();

    // 3) normalize
    for (int i = tid; i < N; i += 256) p[i] *= inv;
}

// ---------------------------------------------------------------------------
extern "C" void kernel_launch(void* const* d_in, const int* in_sizes, int n_in,
                              void* d_out, int out_size)
{
    const float* x  = (const float*)d_in[0];
    const float* Wq = (const float*)d_in[1];
    const float* Wk = (const float*)d_in[2];
    const float* Wv = (const float*)d_in[3];
    float* out = (float*)d_out;

    float *Q, *K, *V, *S;
    cudaGetSymbolAddress((void**)&Q, g_Q);
    cudaGetSymbolAddress((void**)&K, g_K);
    cudaGetSymbolAddress((void**)&V, g_V);
    cudaGetSymbolAddress((void**)&S, g_S);

    dim3 blk(256);
    dim3 gridProj(DIM / 64, SEQ / 64);   // 16 x 64
    dim3 gridScore(SEQ / 64, SEQ / 64);  // 64 x 64
    dim3 gridOut(DIM / 64, SEQ / 64);    // 16 x 64

    // Q, K, V projections (NN)
    sgemm64<false><<<gridProj, blk>>>(x, Wq, Q, SEQ, DIM, DIM, DIM, DIM, DIM, 1.0f);
    sgemm64<false><<<gridProj, blk>>>(x, Wk, K, SEQ, DIM, DIM, DIM, DIM, DIM, 1.0f);
    sgemm64<false><<<gridProj, blk>>>(x, Wv, V, SEQ, DIM, DIM, DIM, DIM, DIM, 1.0f);

    // S = (1/sqrt(DIM)) * Q @ K^T   (NT)
    sgemm64<true><<<gridScore, blk>>>(Q, K, S, SEQ, SEQ, DIM, DIM, DIM, SEQ, 0.03125f);

    // softmax rows
    softmax_rows<<<SEQ, blk>>>(S, SEQ);

    // out = S @ V   (NN)
    sgemm64<false><<<gridOut, blk>>>(S, V, out, SEQ, DIM, SEQ, SEQ, DIM, DIM, 1.0f);
}

// round 3
// speedup vs baseline: 1.3992x; 1.3992x over previous
#include <cuda_runtime.h>
#include <math.h>

#define SEQ 4096
#define DIM 1024

// Static device scratch (no dynamic allocation anywhere).
__device__ float g_Q[SEQ * DIM];
__device__ float g_K[SEQ * DIM];
__device__ float g_V[SEQ * DIM];
__device__ float g_S[(size_t)SEQ * SEQ];

// ---------------------------------------------------------------------------
// SGEMM: C[M,N] = alpha * A[M,K] * op(B)
//   TB=false: B is [K,N] row-major (NN)
//   TB=true : B is [N,K] row-major (NT => C = A * B^T)
// Tiles: 128x128, Kstep=8, 256 threads, 8x8 micro-tile, double-buffered smem.
// Dims assumed divisible by 128/8 (true here: 4096, 1024).
// ---------------------------------------------------------------------------
template <bool TB>
__global__ __launch_bounds__(256, 2) void sgemm128(
    const float* __restrict__ A, const float* __restrict__ B,
    float* __restrict__ C, int M, int N, int Kdim,
    int lda, int ldb, int ldc, float alpha)
{
    __shared__ float As[2][8][128];   // As[buf][k][m]
    __shared__ float Bs[2][8][128];   // Bs[buf][k][n]

    const int tid = threadIdx.x;
    const int tx = tid & 15;          // 0..15 -> 8 cols (two float4 halves)
    const int ty = tid >> 4;          // 0..15 -> 8 rows

    const int row0 = blockIdx.y * 128;
    const int col0 = blockIdx.x * 128;

    // A tile load: 128 rows x 8 k = 256 float4, 1 per thread
    const int ar = tid >> 1;          // 0..127 (tile row)
    const int ac = (tid & 1) * 4;     // 0 or 4 (k)

    // B tile (NN): 8 k x 128 n
    const int br = tid >> 5;          // 0..7 (k)
    const int bc = (tid & 31) * 4;    // 0..124 (n)

    // B tile (NT): 128 n x 8 k
    const int tr = tid >> 1;          // 0..127 (n)
    const int tc = (tid & 1) * 4;     // 0 or 4 (k)

    float acc[8][8];
#pragma unroll
    for (int i = 0; i < 8; i++)
#pragma unroll
        for (int j = 0; j < 8; j++) acc[i][j] = 0.0f;

    const float* Aptr = &A[(size_t)(row0 + ar) * lda + ac];
    const float* BptrNN = &B[(size_t)br * ldb + col0 + bc];
    const float* BptrNT = &B[(size_t)(col0 + tr) * ldb + tc];

    // ---- prologue: load k-tile 0 into buffer 0 ----
    float4 aReg = *reinterpret_cast<const float4*>(Aptr);
    float4 bReg = TB ? *reinterpret_cast<const float4*>(BptrNT)
                     : *reinterpret_cast<const float4*>(BptrNN);

    As[0][ac + 0][ar] = aReg.x;
    As[0][ac + 1][ar] = aReg.y;
    As[0][ac + 2][ar] = aReg.z;
    As[0][ac + 3][ar] = aReg.w;
    if (!TB) {
        *reinterpret_cast<float4*>(&Bs[0][br][bc]) = bReg;
    } else {
        Bs[0][tc + 0][tr] = bReg.x;
        Bs[0][tc + 1][tr] = bReg.y;
        Bs[0][tc + 2][tr] = bReg.z;
        Bs[0][tc + 3][tr] = bReg.w;
    }
    __syncthreads();

    int buf = 0;
    for (int k0 = 0; k0 < Kdim; k0 += 8) {
        const bool more = (k0 + 8) < Kdim;
        // ---- prefetch next k-tile from global into registers ----
        if (more) {
            aReg = *reinterpret_cast<const float4*>(Aptr + (k0 + 8));
            bReg = TB ? *reinterpret_cast<const float4*>(BptrNT + (k0 + 8))
                      : *reinterpret_cast<const float4*>(BptrNN + (size_t)(k0 + 8) * ldb);
        }

        // ---- compute on current buffer ----
#pragma unroll
        for (int k = 0; k < 8; k++) {
            float4 a0 = *reinterpret_cast<const float4*>(&As[buf][k][ty * 4]);
            float4 a1 = *reinterpret_cast<const float4*>(&As[buf][k][64 + ty * 4]);
            float4 b0 = *reinterpret_cast<const float4*>(&Bs[buf][k][tx * 4]);
            float4 b1 = *reinterpret_cast<const float4*>(&Bs[buf][k][64 + tx * 4]);
            float av[8] = {a0.x, a0.y, a0.z, a0.w, a1.x, a1.y, a1.z, a1.w};
            float bv[8] = {b0.x, b0.y, b0.z, b0.w, b1.x, b1.y, b1.z, b1.w};
#pragma unroll
            for (int i = 0; i < 8; i++)
#pragma unroll
                for (int j = 0; j < 8; j++)
                    acc[i][j] = fmaf(av[i], bv[j], acc[i][j]);
        }

        // ---- store prefetched tile into other buffer ----
        if (more) {
            buf ^= 1;
            As[buf][ac + 0][ar] = aReg.x;
            As[buf][ac + 1][ar] = aReg.y;
            As[buf][ac + 2][ar] = aReg.z;
            As[buf][ac + 3][ar] = aReg.w;
            if (!TB) {
                *reinterpret_cast<float4*>(&Bs[buf][br][bc]) = bReg;
            } else {
                Bs[buf][tc + 0][tr] = bReg.x;
                Bs[buf][tc + 1][tr] = bReg.y;
                Bs[buf][tc + 2][tr] = bReg.z;
                Bs[buf][tc + 3][tr] = bReg.w;
            }
            __syncthreads();
        }
    }

    // ---- epilogue ----
#pragma unroll
    for (int i = 0; i < 8; i++) {
        const int r = row0 + ty * 4 + (i & 3) + ((i >> 2) * 64);
        float4 o0, o1;
        o0.x = alpha * acc[i][0];
        o0.y = alpha * acc[i][1];
        o0.z = alpha * acc[i][2];
        o0.w = alpha * acc[i][3];
        o1.x = alpha * acc[i][4];
        o1.y = alpha * acc[i][5];
        o1.z = alpha * acc[i][6];
        o1.w = alpha * acc[i][7];
        *reinterpret_cast<float4*>(&C[(size_t)r * ldc + col0 + tx * 4]) = o0;
        *reinterpret_cast<float4*>(&C[(size_t)r * ldc + col0 + 64 + tx * 4]) = o1;
    }
}

// ---------------------------------------------------------------------------
// Row softmax over S[SEQ, SEQ], one block per row.
// ---------------------------------------------------------------------------
__global__ __launch_bounds__(256) void softmax_rows(float* __restrict__ S, int N)
{
    const int row = blockIdx.x;
    float* p = S + (size_t)row * N;
    const int tid = threadIdx.x;
    __shared__ float red[256];

    float mx = -INFINITY;
    for (int i = tid; i < N; i += 256) mx = fmaxf(mx, p[i]);
    red[tid] = mx;
    __syncthreads();
#pragma unroll
    for (int s = 128; s > 0; s >>= 1) {
        if (tid < s) red[tid] = fmaxf(red[tid], red[tid + s]);
        __syncthreads();
    }
    mx = red[0];
    __syncthreads();

    float sum = 0.0f;
    for (int i = tid; i < N; i += 256) {
        float e = expf(p[i] - mx);
        p[i] = e;
        sum += e;
    }
    red[tid] = sum;
    __syncthreads();
#pragma unroll
    for (int s = 128; s > 0; s >>= 1) {
        if (tid < s) red[tid] += red[tid + s];
        __syncthreads();
    }
    const float inv = 1.0f / red[0];
    __syncthreads();

    for (int i = tid; i < N; i += 256) p[i] *= inv;
}

// ---------------------------------------------------------------------------
extern "C" void kernel_launch(void* const* d_in, const int* in_sizes, int n_in,
                              void* d_out, int out_size)
{
    const float* x  = (const float*)d_in[0];
    const float* Wq = (const float*)d_in[1];
    const float* Wk = (const float*)d_in[2];
    const float* Wv = (const float*)d_in[3];
    float* out = (float*)d_out;

    float *Q, *K, *V, *S;
    cudaGetSymbolAddress((void**)&Q, g_Q);
    cudaGetSymbolAddress((void**)&K, g_K);
    cudaGetSymbolAddress((void**)&V, g_V);
    cudaGetSymbolAddress((void**)&S, g_S);

    dim3 blk(256);
    dim3 gridProj(DIM / 128, SEQ / 128);   // 8 x 32
    dim3 gridScore(SEQ / 128, SEQ / 128);  // 32 x 32
    dim3 gridOut(DIM / 128, SEQ / 128);    // 8 x 32

    // Q, K, V projections (NN)
    sgemm128<false><<<gridProj, blk>>>(x, Wq, Q, SEQ, DIM, DIM, DIM, DIM, DIM, 1.0f);
    sgemm128<false><<<gridProj, blk>>>(x, Wk, K, SEQ, DIM, DIM, DIM, DIM, DIM, 1.0f);
    sgemm128<false><<<gridProj, blk>>>(x, Wv, V, SEQ, DIM, DIM, DIM, DIM, DIM, 1.0f);

    // S = (1/sqrt(DIM)) * Q @ K^T   (NT)
    sgemm128<true><<<gridScore, blk>>>(Q, K, S, SEQ, SEQ, DIM, DIM, DIM, SEQ, 0.03125f);

    // softmax rows
    softmax_rows<<<SEQ, blk>>>(S, SEQ);

    // out = S @ V   (NN)
    sgemm128<false><<<gridOut, blk>>>(S, V, out, SEQ, DIM, SEQ, SEQ, DIM, DIM, 1.0f);
}

// round 6
// speedup vs baseline: 2.5871x; 1.8490x over previous
#include <cuda_runtime.h>
#include <cuda_fp16.h>
#include <stdint.h>
#include <math.h>

#define SEQ 4096
#define DIM 1024

typedef __half h16;

// ---------------- static device scratch ----------------
__device__ h16  g_xp[2][SEQ * DIM];
__device__ h16  g_Wqt[2][DIM * DIM];
__device__ h16  g_Wkt[2][DIM * DIM];
__device__ h16  g_Wvt[2][DIM * DIM];
__device__ h16  g_Qp[2][SEQ * DIM];
__device__ h16  g_Kp[2][SEQ * DIM];
__device__ float g_V[SEQ * DIM];
__device__ h16  g_Vt[2][(size_t)DIM * SEQ];
__device__ float g_S[(size_t)SEQ * SEQ];
__device__ h16  g_Pp[2][(size_t)SEQ * SEQ];

// ---------------- helpers ----------------
__device__ __forceinline__ uint32_t smem_u32(const void* p) {
    uint32_t a;
    asm("{ .reg .u64 t; cvta.to.shared.u64 t, %1; cvt.u32.u64 %0, t; }" : "=r"(a) : "l"(p));
    return a;
}
__device__ __forceinline__ uint32_t sw128(uint32_t o) { return o ^ ((o >> 3) & 0x70); }

__device__ __forceinline__ void cp_async16(uint32_t s, const void* g) {
    asm volatile("cp.async.cg.shared.global [%0], [%1], 16;" :: "r"(s), "l"(g));
}
#define CP_COMMIT() asm volatile("cp.async.commit_group;" ::: "memory")
#define CP_WAIT1()  asm volatile("cp.async.wait_group 1;" ::: "memory")

__device__ __forceinline__ void ldsm4(uint32_t& r0, uint32_t& r1, uint32_t& r2, uint32_t& r3, uint32_t a) {
    asm volatile("ldmatrix.sync.aligned.m8n8.x4.shared.b16 {%0,%1,%2,%3}, [%4];"
                 : "=r"(r0), "=r"(r1), "=r"(r2), "=r"(r3) : "r"(a));
}
__device__ __forceinline__ void mma16816(float* c, const uint32_t* a, const uint32_t* b) {
    asm volatile("mma.sync.aligned.m16n8k16.row.col.f32.f16.f16.f32 "
                 "{%0,%1,%2,%3}, {%4,%5,%6,%7}, {%8,%9}, {%0,%1,%2,%3};"
                 : "+f"(c[0]), "+f"(c[1]), "+f"(c[2]), "+f"(c[3])
                 : "r"(a[0]), "r"(a[1]), "r"(a[2]), "r"(a[3]), "r"(b[0]), "r"(b[1]));
}
__device__ __forceinline__ void split2(float v, h16& x0, h16& x1) {
    x0 = __float2half_rn(v);
    x1 = __float2half_rn(v - __half2float(x0));
}

// ---------------------------------------------------------------------------
// HMMA GEMM:  C[M,N] = alpha * A[M,K] * B[N,K]^T   (both K-major fp16 planes)
// 2-plane fp16 split; 3 products via K-segment concatenation:
//   seg0: a0*b0, seg1: a0*b1, seg2: a1*b0
// Tile 128x128, BK=64, cp.async double buffer, 256 threads (2x4 warps, 64x32).
// EPI=0: write fp32 C (alpha-scaled). EPI=1: write 2 fp16 split planes.
// ---------------------------------------------------------------------------
template <int EPI>
__global__ __launch_bounds__(256, 1) void gemm_hmma(
    const h16* __restrict__ a0, const h16* __restrict__ a1,
    const h16* __restrict__ b0, const h16* __restrict__ b1,
    float* __restrict__ C, h16* __restrict__ c0, h16* __restrict__ c1,
    int M, int N, int Kd, float alpha)
{
    extern __shared__ char sm[];
    const uint32_t smu = smem_u32(sm);
    const int tid = threadIdx.x;
    const int wid = tid >> 5, lane = tid & 31;
    const int wm = wid >> 2, wn = wid & 3;             // 2x4 warp grid
    const int row0 = blockIdx.y * 128, col0 = blockIdx.x * 128;

    const h16* segA[3] = {a0, a0, a1};
    const h16* segB[3] = {b0, b1, b0};
    const int cpk = Kd >> 6;       // chunks per segment
    const int nc = 3 * cpk;

    // global->smem mapping: 128 rows x 8 x 16B granules per tile, 4 per thread
    const int gr = tid >> 3;       // base row (0..31), +32 per q
    const int gc = tid & 7;        // granule

    float acc[4][4][4];
#pragma unroll
    for (int i = 0; i < 4; i++)
#pragma unroll
        for (int j = 0; j < 4; j++)
#pragma unroll
            for (int q = 0; q < 4; q++) acc[i][j][q] = 0.0f;

    auto load_chunk = [&](int c, int b) {
        const int seg = c / cpk;
        const int kc = (c - seg * cpk) << 6;
        const h16* Ag = segA[seg];
        const h16* Bg = segB[seg];
        const uint32_t abase = smu + (uint32_t)b * 32768u;
        const uint32_t bbase = abase + 16384u;
#pragma unroll
        for (int q = 0; q < 4; q++) {
            const int r = gr + q * 32;
            const uint32_t off = sw128((uint32_t)(r * 128 + gc * 16));
            cp_async16(abase + off, Ag + (size_t)(row0 + r) * Kd + kc + gc * 8);
            cp_async16(bbase + off, Bg + (size_t)(col0 + r) * Kd + kc + gc * 8);
        }
        CP_COMMIT();
    };

    load_chunk(0, 0);
    load_chunk(1, 1);

    for (int c = 0; c < nc; c++) {
        CP_WAIT1();
        __syncthreads();

        const uint32_t ab = smu + (uint32_t)(c & 1) * 32768u;
        const uint32_t bb = ab + 16384u;

#pragma unroll
        for (int ks = 0; ks < 4; ks++) {
            uint32_t af[4][4];
            uint32_t bf[4][2];
#pragma unroll
            for (int mt = 0; mt < 4; mt++) {
                const int rr = wm * 64 + mt * 16 + (lane & 15);
                const uint32_t off = sw128((uint32_t)(rr * 128 + ks * 32 + ((lane >> 4) << 4)));
                ldsm4(af[mt][0], af[mt][1], af[mt][2], af[mt][3], ab + off);
            }
#pragma unroll
            for (int nt2 = 0; nt2 < 2; nt2++) {
                const int nn = wn * 32 + nt2 * 16 + ((lane >> 4) << 3) + (lane & 7);
                const uint32_t off = sw128((uint32_t)(nn * 128 + ks * 32 + (((lane >> 3) & 1) << 4)));
                uint32_t r0, r1, r2, r3;
                ldsm4(r0, r1, r2, r3, bb + off);
                bf[nt2 * 2][0] = r0;     bf[nt2 * 2][1] = r1;
                bf[nt2 * 2 + 1][0] = r2; bf[nt2 * 2 + 1][1] = r3;
            }
#pragma unroll
            for (int mt = 0; mt < 4; mt++)
#pragma unroll
                for (int nt = 0; nt < 4; nt++)
                    mma16816(acc[mt][nt], af[mt], bf[nt]);
        }

        __syncthreads();
        if (c + 2 < nc) load_chunk(c + 2, c & 1);
        else CP_COMMIT();      // keep group count consistent for CP_WAIT1
    }

    // ---- epilogue ----
    const int gid = lane >> 2, tig = lane & 3;
#pragma unroll
    for (int mt = 0; mt < 4; mt++) {
        const int r_ = row0 + wm * 64 + mt * 16 + gid;
#pragma unroll
        for (int nt = 0; nt < 4; nt++) {
            const int cc = col0 + wn * 32 + nt * 8 + tig * 2;
            const float v0 = alpha * acc[mt][nt][0];
            const float v1 = alpha * acc[mt][nt][1];
            const float v2 = alpha * acc[mt][nt][2];
            const float v3 = alpha * acc[mt][nt][3];
            if (EPI == 0) {
                *reinterpret_cast<float2*>(&C[(size_t)r_ * N + cc]) = make_float2(v0, v1);
                *reinterpret_cast<float2*>(&C[(size_t)(r_ + 8) * N + cc]) = make_float2(v2, v3);
            } else {
                h16 p0, p1, q0, q1;
                split2(v0, p0, p1); split2(v1, q0, q1);
                __half2 lo0; lo0.x = p0; lo0.y = q0;
                __half2 lo1; lo1.x = p1; lo1.y = q1;
                *reinterpret_cast<__half2*>(c0 + (size_t)r_ * N + cc) = lo0;
                *reinterpret_cast<__half2*>(c1 + (size_t)r_ * N + cc) = lo1;
                split2(v2, p0, p1); split2(v3, q0, q1);
                __half2 hi0; hi0.x = p0; hi0.y = q0;
                __half2 hi1; hi1.x = p1; hi1.y = q1;
                *reinterpret_cast<__half2*>(c0 + (size_t)(r_ + 8) * N + cc) = hi0;
                *reinterpret_cast<__half2*>(c1 + (size_t)(r_ + 8) * N + cc) = hi1;
            }
        }
    }
}

#define GEMM_SMEM 65536

// ---------------------------------------------------------------------------
// fp32 -> 2 fp16 planes
// ---------------------------------------------------------------------------
__global__ __launch_bounds__(256) void split_planes2(
    const float* __restrict__ src, h16* __restrict__ d0, h16* __restrict__ d1, int n)
{
    int i = (blockIdx.x * 256 + threadIdx.x) * 2;
    if (i < n) {
        float2 v = *reinterpret_cast<const float2*>(src + i);
        h16 a0, a1, b0, b1;
        split2(v.x, a0, a1); split2(v.y, b0, b1);
        __half2 p0; p0.x = a0; p0.y = b0;
        __half2 p1; p1.x = a1; p1.y = b1;
        *reinterpret_cast<__half2*>(d0 + i) = p0;
        *reinterpret_cast<__half2*>(d1 + i) = p1;
    }
}

// ---------------------------------------------------------------------------
// fp32 [R,C] -> transposed 2 fp16 planes [C,R]
// ---------------------------------------------------------------------------
__global__ __launch_bounds__(256) void transpose_split2(
    const float* __restrict__ src, h16* __restrict__ d0, h16* __restrict__ d1, int R, int C)
{
    __shared__ float t[32][33];
    const int tx = threadIdx.x, ty = threadIdx.y;
    const int r0 = blockIdx.y * 32, c0 = blockIdx.x * 32;
#pragma unroll
    for (int j = 0; j < 32; j += 8)
        t[ty + j][tx] = src[(size_t)(r0 + ty + j) * C + c0 + tx];
    __syncthreads();
#pragma unroll
    for (int j = 0; j < 32; j += 8) {
        float v = t[tx][ty + j];
        h16 h0, h1;
        split2(v, h0, h1);
        size_t o = (size_t)(c0 + ty + j) * R + r0 + tx;
        d0[o] = h0; d1[o] = h1;
    }
}

// ---------------------------------------------------------------------------
// Row softmax over S[SEQ,SEQ]; writes 2 fp16 split planes of the weights.
// ---------------------------------------------------------------------------
__global__ __launch_bounds__(256) void softmax_split2(
    float* __restrict__ S, h16* __restrict__ P0, h16* __restrict__ P1)
{
    const int row = blockIdx.x;
    float* p = S + (size_t)row * SEQ;
    const int tid = threadIdx.x;
    __shared__ float red[256];

    float mx = -INFINITY;
    for (int i = tid; i < SEQ; i += 256) mx = fmaxf(mx, p[i]);
    red[tid] = mx;
    __syncthreads();
#pragma unroll
    for (int s = 128; s > 0; s >>= 1) {
        if (tid < s) red[tid] = fmaxf(red[tid], red[tid + s]);
        __syncthreads();
    }
    mx = red[0];
    __syncthreads();

    float sum = 0.0f;
    for (int i = tid; i < SEQ; i += 256) {
        float e = expf(p[i] - mx);
        p[i] = e;
        sum += e;
    }
    red[tid] = sum;
    __syncthreads();
#pragma unroll
    for (int s = 128; s > 0; s >>= 1) {
        if (tid < s) red[tid] += red[tid + s];
        __syncthreads();
    }
    const float inv = 1.0f / red[0];
    __syncthreads();

    const size_t base = (size_t)row * SEQ;
    for (int i = tid * 2; i < SEQ; i += 512) {
        float w0 = p[i] * inv;
        float w1 = p[i + 1] * inv;
        h16 a0, a1, b0, b1;
        split2(w0, a0, a1); split2(w1, b0, b1);
        __half2 q0; q0.x = a0; q0.y = b0;
        __half2 q1; q1.x = a1; q1.y = b1;
        *reinterpret_cast<__half2*>(P0 + base + i) = q0;
        *reinterpret_cast<__half2*>(P1 + base + i) = q1;
    }
}

// ---------------------------------------------------------------------------
extern "C" void kernel_launch(void* const* d_in, const int* in_sizes, int n_in,
                              void* d_out, int out_size)
{
    const float* x  = (const float*)d_in[0];
    const float* Wq = (const float*)d_in[1];
    const float* Wk = (const float*)d_in[2];
    const float* Wv = (const float*)d_in[3];
    float* out = (float*)d_out;

    h16 *xp, *wqt, *wkt, *wvt, *qp, *kp, *vt, *pp;
    float *V, *S;
    cudaGetSymbolAddress((void**)&xp,  g_xp);
    cudaGetSymbolAddress((void**)&wqt, g_Wqt);
    cudaGetSymbolAddress((void**)&wkt, g_Wkt);
    cudaGetSymbolAddress((void**)&wvt, g_Wvt);
    cudaGetSymbolAddress((void**)&qp,  g_Qp);
    cudaGetSymbolAddress((void**)&kp,  g_Kp);
    cudaGetSymbolAddress((void**)&V,   g_V);
    cudaGetSymbolAddress((void**)&vt,  g_Vt);
    cudaGetSymbolAddress((void**)&S,   g_S);
    cudaGetSymbolAddress((void**)&pp,  g_Pp);

    const size_t ND = (size_t)SEQ * DIM;
    const size_t DD = (size_t)DIM * DIM;
    const size_t NN = (size_t)SEQ * SEQ;

    h16 *xp0 = xp, *xp1 = xp + ND;
    h16 *wq0 = wqt, *wq1 = wqt + DD;
    h16 *wk0 = wkt, *wk1 = wkt + DD;
    h16 *wv0 = wvt, *wv1 = wvt + DD;
    h16 *qp0 = qp, *qp1 = qp + ND;
    h16 *kp0 = kp, *kp1 = kp + ND;
    h16 *vt0 = vt, *vt1 = vt + ND;
    h16 *pp0 = pp, *pp1 = pp + NN;

    cudaFuncSetAttribute(gemm_hmma<0>, cudaFuncAttributeMaxDynamicSharedMemorySize, GEMM_SMEM);
    cudaFuncSetAttribute(gemm_hmma<1>, cudaFuncAttributeMaxDynamicSharedMemorySize, GEMM_SMEM);

    dim3 b256(256);
    dim3 tb(32, 8);

    // 1) split inputs
    split_planes2<<<(int)(ND / 512), b256>>>(x, xp0, xp1, (int)ND);
    transpose_split2<<<dim3(DIM / 32, DIM / 32), tb>>>(Wq, wq0, wq1, DIM, DIM);
    transpose_split2<<<dim3(DIM / 32, DIM / 32), tb>>>(Wk, wk0, wk1, DIM, DIM);
    transpose_split2<<<dim3(DIM / 32, DIM / 32), tb>>>(Wv, wv0, wv1, DIM, DIM);

    // 2) projections: Q,K -> split planes; V -> fp32
    dim3 gProj(DIM / 128, SEQ / 128);
    gemm_hmma<1><<<gProj, b256, GEMM_SMEM>>>(xp0, xp1, wq0, wq1,
                                             nullptr, qp0, qp1, SEQ, DIM, DIM, 1.0f);
    gemm_hmma<1><<<gProj, b256, GEMM_SMEM>>>(xp0, xp1, wk0, wk1,
                                             nullptr, kp0, kp1, SEQ, DIM, DIM, 1.0f);
    gemm_hmma<0><<<gProj, b256, GEMM_SMEM>>>(xp0, xp1, wv0, wv1,
                                             V, nullptr, nullptr, SEQ, DIM, DIM, 1.0f);

    // 3) scores S = (1/32) Q K^T
    dim3 gScore(SEQ / 128, SEQ / 128);
    gemm_hmma<0><<<gScore, b256, GEMM_SMEM>>>(qp0, qp1, kp0, kp1,
                                              S, nullptr, nullptr, SEQ, SEQ, DIM, 0.03125f);

    // 4) softmax + split P
    softmax_split2<<<SEQ, b256>>>(S, pp0, pp1);

    // 5) V^T planes
    transpose_split2<<<dim3(DIM / 32, SEQ / 32), tb>>>(V, vt0, vt1, SEQ, DIM);

    // 6) out = P V
    dim3 gOut(DIM / 128, SEQ / 128);
    gemm_hmma<0><<<gOut, b256, GEMM_SMEM>>>(pp0, pp1, vt0, vt1,
                                            out, nullptr, nullptr, SEQ, DIM, SEQ, 1.0f);
}

// round 7
// speedup vs baseline: 3.1249x; 1.2079x over previous
#include <cuda_runtime.h>
#include <cuda_fp16.h>
#include <stdint.h>
#include <math.h>

#define SEQ 4096
#define DIM 1024

typedef __half h16;

// ---------------- static device scratch ----------------
__device__ h16  g_xp[2][SEQ * DIM];                 // x split planes [SEQ, DIM]
__device__ h16  g_Wqkt[2][2 * DIM * DIM];           // [Wq^T ; Wk^T] planes [2048, 1024]
__device__ h16  g_Wvt[2][DIM * DIM];                // Wv^T planes [1024, 1024]
__device__ h16  g_QKp[2][(size_t)SEQ * 2 * DIM];    // [Q | K] planes [SEQ, 2048]
__device__ h16  g_Vt[2][(size_t)DIM * SEQ];         // V^T planes [DIM, SEQ]
__device__ float g_S[(size_t)SEQ * SEQ];
__device__ h16  g_Pp[2][(size_t)SEQ * SEQ];

// ---------------- helpers ----------------
__device__ __forceinline__ uint32_t smem_u32(const void* p) {
    uint32_t a;
    asm("{ .reg .u64 t; cvta.to.shared.u64 t, %1; cvt.u32.u64 %0, t; }" : "=r"(a) : "l"(p));
    return a;
}
__device__ __forceinline__ uint32_t sw128(uint32_t o) { return o ^ ((o >> 3) & 0x70); }

__device__ __forceinline__ void cp_async16(uint32_t s, const void* g) {
    asm volatile("cp.async.cg.shared.global [%0], [%1], 16;" :: "r"(s), "l"(g));
}
#define CP_COMMIT() asm volatile("cp.async.commit_group;" ::: "memory")
#define CP_WAIT1()  asm volatile("cp.async.wait_group 1;" ::: "memory")

__device__ __forceinline__ void ldsm4(uint32_t& r0, uint32_t& r1, uint32_t& r2, uint32_t& r3, uint32_t a) {
    asm volatile("ldmatrix.sync.aligned.m8n8.x4.shared.b16 {%0,%1,%2,%3}, [%4];"
                 : "=r"(r0), "=r"(r1), "=r"(r2), "=r"(r3) : "r"(a));
}
__device__ __forceinline__ void mma16816(float* c, const uint32_t* a, const uint32_t* b) {
    asm volatile("mma.sync.aligned.m16n8k16.row.col.f32.f16.f16.f32 "
                 "{%0,%1,%2,%3}, {%4,%5,%6,%7}, {%8,%9}, {%0,%1,%2,%3};"
                 : "+f"(c[0]), "+f"(c[1]), "+f"(c[2]), "+f"(c[3])
                 : "r"(a[0]), "r"(a[1]), "r"(a[2]), "r"(a[3]), "r"(b[0]), "r"(b[1]));
}
__device__ __forceinline__ void split2(float v, h16& x0, h16& x1) {
    x0 = __float2half_rn(v);
    x1 = __float2half_rn(v - __half2float(x0));
}

// ---------------------------------------------------------------------------
// HMMA GEMM:  C[M,N] = alpha * A[M,K] * B[N,K]^T   (both K-major fp16 planes)
// 2-plane split, 3 products via K-segment concat: a0b0, a0b1, a1b0.
// CTA tile 256x128, BK=64, 8 warps (4x2 grid of 64x64 warp tiles),
// cp.async double buffer (2 x 48KB). EPI=0: fp32 C; EPI=1: 2 fp16 planes.
// M from gridDim.y*256. Leading dims lda/ldb/ldc decouple layout from K extent.
// ---------------------------------------------------------------------------
template <int EPI>
__global__ __launch_bounds__(256, 1) void gemm_hmma(
    const h16* __restrict__ a0, const h16* __restrict__ a1,
    const h16* __restrict__ b0, const h16* __restrict__ b1,
    float* __restrict__ C, h16* __restrict__ c0, h16* __restrict__ c1,
    int N, int Kd, int lda, int ldb, int ldc, float alpha)
{
    extern __shared__ char sm[];
    const uint32_t smu = smem_u32(sm);
    const int tid = threadIdx.x;
    const int wid = tid >> 5, lane = tid & 31;
    const int wm = wid >> 1, wn = wid & 1;            // 4x2 warp grid, 64x64 tiles
    const int row0 = blockIdx.y * 256, col0 = blockIdx.x * 128;

    const h16* segA[3] = {a0, a0, a1};
    const h16* segB[3] = {b0, b1, b0};
    const int cpk = Kd >> 6;
    const int nc = 3 * cpk;

    const int gr = tid >> 3;       // 0..31 base row
    const int gc = tid & 7;        // 16B granule in 128B row

    float acc[4][8][4];
#pragma unroll
    for (int i = 0; i < 4; i++)
#pragma unroll
        for (int j = 0; j < 8; j++)
#pragma unroll
            for (int q = 0; q < 4; q++) acc[i][j][q] = 0.0f;

    auto load_chunk = [&](int c, int b) {
        const int seg = c / cpk;
        const int kc = (c - seg * cpk) << 6;
        const h16* Ag = segA[seg];
        const h16* Bg = segB[seg];
        const uint32_t abase = smu + (uint32_t)b * 49152u;   // 48KB stage
        const uint32_t bbase = abase + 32768u;               // A:32KB then B:16KB
#pragma unroll
        for (int q = 0; q < 8; q++) {                        // A: 256 rows
            const int r = gr + q * 32;
            const uint32_t off = sw128((uint32_t)(r * 128 + gc * 16));
            cp_async16(abase + off, Ag + (size_t)(row0 + r) * lda + kc + gc * 8);
        }
#pragma unroll
        for (int q = 0; q < 4; q++) {                        // B: 128 rows
            const int r = gr + q * 32;
            const uint32_t off = sw128((uint32_t)(r * 128 + gc * 16));
            cp_async16(bbase + off, Bg + (size_t)(col0 + r) * ldb + kc + gc * 8);
        }
        CP_COMMIT();
    };

    load_chunk(0, 0);
    load_chunk(1, 1);

    for (int c = 0; c < nc; c++) {
        CP_WAIT1();
        __syncthreads();

        const uint32_t ab = smu + (uint32_t)(c & 1) * 49152u;
        const uint32_t bb = ab + 32768u;

#pragma unroll
        for (int ks = 0; ks < 4; ks++) {
            uint32_t af[4][4];
            uint32_t bf[8][2];
#pragma unroll
            for (int mt = 0; mt < 4; mt++) {
                const int rr = wm * 64 + mt * 16 + (lane & 15);
                const uint32_t off = sw128((uint32_t)(rr * 128 + ks * 32 + ((lane >> 4) << 4)));
                ldsm4(af[mt][0], af[mt][1], af[mt][2], af[mt][3], ab + off);
            }
#pragma unroll
            for (int nt2 = 0; nt2 < 4; nt2++) {
                const int nn = wn * 64 + nt2 * 16 + ((lane >> 4) << 3) + (lane & 7);
                const uint32_t off = sw128((uint32_t)(nn * 128 + ks * 32 + (((lane >> 3) & 1) << 4)));
                uint32_t r0, r1, r2, r3;
                ldsm4(r0, r1, r2, r3, bb + off);
                bf[nt2 * 2][0] = r0;     bf[nt2 * 2][1] = r1;
                bf[nt2 * 2 + 1][0] = r2; bf[nt2 * 2 + 1][1] = r3;
            }
#pragma unroll
            for (int mt = 0; mt < 4; mt++)
#pragma unroll
                for (int nt = 0; nt < 8; nt++)
                    mma16816(acc[mt][nt], af[mt], bf[nt]);
        }

        __syncthreads();
        if (c + 2 < nc) load_chunk(c + 2, c & 1);
        else CP_COMMIT();
    }

    // ---- epilogue ----
    const int gid = lane >> 2, tig = lane & 3;
#pragma unroll
    for (int mt = 0; mt < 4; mt++) {
        const int r_ = row0 + wm * 64 + mt * 16 + gid;
#pragma unroll
        for (int nt = 0; nt < 8; nt++) {
            const int cc = col0 + wn * 64 + nt * 8 + tig * 2;
            const float v0 = alpha * acc[mt][nt][0];
            const float v1 = alpha * acc[mt][nt][1];
            const float v2 = alpha * acc[mt][nt][2];
            const float v3 = alpha * acc[mt][nt][3];
            if (EPI == 0) {
                *reinterpret_cast<float2*>(&C[(size_t)r_ * ldc + cc]) = make_float2(v0, v1);
                *reinterpret_cast<float2*>(&C[(size_t)(r_ + 8) * ldc + cc]) = make_float2(v2, v3);
            } else {
                h16 p0, p1, q0, q1;
                split2(v0, p0, p1); split2(v1, q0, q1);
                __half2 lo0; lo0.x = p0; lo0.y = q0;
                __half2 lo1; lo1.x = p1; lo1.y = q1;
                *reinterpret_cast<__half2*>(c0 + (size_t)r_ * ldc + cc) = lo0;
                *reinterpret_cast<__half2*>(c1 + (size_t)r_ * ldc + cc) = lo1;
                split2(v2, p0, p1); split2(v3, q0, q1);
                __half2 hi0; hi0.x = p0; hi0.y = q0;
                __half2 hi1; hi1.x = p1; hi1.y = q1;
                *reinterpret_cast<__half2*>(c0 + (size_t)(r_ + 8) * ldc + cc) = hi0;
                *reinterpret_cast<__half2*>(c1 + (size_t)(r_ + 8) * ldc + cc) = hi1;
            }
        }
    }
}

#define GEMM_SMEM 98304

// ---------------------------------------------------------------------------
__global__ __launch_bounds__(256) void split_planes2(
    const float* __restrict__ src, h16* __restrict__ d0, h16* __restrict__ d1, int n)
{
    int i = (blockIdx.x * 256 + threadIdx.x) * 2;
    if (i < n) {
        float2 v = *reinterpret_cast<const float2*>(src + i);
        h16 a0, a1, b0, b1;
        split2(v.x, a0, a1); split2(v.y, b0, b1);
        __half2 p0; p0.x = a0; p0.y = b0;
        __half2 p1; p1.x = a1; p1.y = b1;
        *reinterpret_cast<__half2*>(d0 + i) = p0;
        *reinterpret_cast<__half2*>(d1 + i) = p1;
    }
}

// fp32 [R,C] -> transposed 2 fp16 planes [C,R]
__global__ __launch_bounds__(256) void transpose_split2(
    const float* __restrict__ src, h16* __restrict__ d0, h16* __restrict__ d1, int R, int C)
{
    __shared__ float t[32][33];
    const int tx = threadIdx.x, ty = threadIdx.y;
    const int r0 = blockIdx.y * 32, c0 = blockIdx.x * 32;
#pragma unroll
    for (int j = 0; j < 32; j += 8)
        t[ty + j][tx] = src[(size_t)(r0 + ty + j) * C + c0 + tx];
    __syncthreads();
#pragma unroll
    for (int j = 0; j < 32; j += 8) {
        float v = t[tx][ty + j];
        h16 h0, h1;
        split2(v, h0, h1);
        size_t o = (size_t)(c0 + ty + j) * R + r0 + tx;
        d0[o] = h0; d1[o] = h1;
    }
}

// ---------------------------------------------------------------------------
// Row softmax; writes 2 fp16 split planes of the weights.
// ---------------------------------------------------------------------------
__global__ __launch_bounds__(256) void softmax_split2(
    float* __restrict__ S, h16* __restrict__ P0, h16* __restrict__ P1)
{
    const int row = blockIdx.x;
    float* p = S + (size_t)row * SEQ;
    const int tid = threadIdx.x;
    __shared__ float red[256];

    float mx = -INFINITY;
    for (int i = tid; i < SEQ; i += 256) mx = fmaxf(mx, p[i]);
    red[tid] = mx;
    __syncthreads();
#pragma unroll
    for (int s = 128; s > 0; s >>= 1) {
        if (tid < s) red[tid] = fmaxf(red[tid], red[tid + s]);
        __syncthreads();
    }
    mx = red[0];
    __syncthreads();

    float sum = 0.0f;
    for (int i = tid; i < SEQ; i += 256) {
        float e = expf(p[i] - mx);
        p[i] = e;
        sum += e;
    }
    red[tid] = sum;
    __syncthreads();
#pragma unroll
    for (int s = 128; s > 0; s >>= 1) {
        if (tid < s) red[tid] += red[tid + s];
        __syncthreads();
    }
    const float inv = 1.0f / red[0];
    __syncthreads();

    const size_t base = (size_t)row * SEQ;
    for (int i = tid * 2; i < SEQ; i += 512) {
        float w0 = p[i] * inv;
        float w1 = p[i + 1] * inv;
        h16 a0, a1, b0, b1;
        split2(w0, a0, a1); split2(w1, b0, b1);
        __half2 q0; q0.x = a0; q0.y = b0;
        __half2 q1; q1.x = a1; q1.y = b1;
        *reinterpret_cast<__half2*>(P0 + base + i) = q0;
        *reinterpret_cast<__half2*>(P1 + base + i) = q1;
    }
}

// ---------------------------------------------------------------------------
extern "C" void kernel_launch(void* const* d_in, const int* in_sizes, int n_in,
                              void* d_out, int out_size)
{
    const float* x  = (const float*)d_in[0];
    const float* Wq = (const float*)d_in[1];
    const float* Wk = (const float*)d_in[2];
    const float* Wv = (const float*)d_in[3];
    float* out = (float*)d_out;

    h16 *xp, *wqkt, *wvt, *qkp, *vt, *pp;
    float *S;
    cudaGetSymbolAddress((void**)&xp,   g_xp);
    cudaGetSymbolAddress((void**)&wqkt, g_Wqkt);
    cudaGetSymbolAddress((void**)&wvt,  g_Wvt);
    cudaGetSymbolAddress((void**)&qkp,  g_QKp);
    cudaGetSymbolAddress((void**)&vt,   g_Vt);
    cudaGetSymbolAddress((void**)&S,    g_S);
    cudaGetSymbolAddress((void**)&pp,   g_Pp);

    const size_t ND = (size_t)SEQ * DIM;      // 4M
    const size_t DD = (size_t)DIM * DIM;      // 1M
    const size_t N2 = (size_t)SEQ * 2 * DIM;  // 8M
    const size_t NN = (size_t)SEQ * SEQ;      // 16M

    h16 *xp0 = xp, *xp1 = xp + ND;
    h16 *wqk0 = wqkt, *wqk1 = wqkt + 2 * DD;
    h16 *wv0 = wvt, *wv1 = wvt + DD;
    h16 *qk0 = qkp, *qk1 = qkp + N2;
    h16 *vt0 = vt, *vt1 = vt + ND;
    h16 *pp0 = pp, *pp1 = pp + NN;

    cudaFuncSetAttribute(gemm_hmma<0>, cudaFuncAttributeMaxDynamicSharedMemorySize, GEMM_SMEM);
    cudaFuncSetAttribute(gemm_hmma<1>, cudaFuncAttributeMaxDynamicSharedMemorySize, GEMM_SMEM);

    dim3 b256(256);
    dim3 tb(32, 8);

    // 1) split x; transpose-split weights (Wq,Wk fused into one [2048,1024] buffer)
    split_planes2<<<(int)(ND / 512), b256>>>(x, xp0, xp1, (int)ND);
    transpose_split2<<<dim3(DIM / 32, DIM / 32), tb>>>(Wq, wqk0, wqk1, DIM, DIM);
    transpose_split2<<<dim3(DIM / 32, DIM / 32), tb>>>(Wk, wqk0 + DD, wqk1 + DD, DIM, DIM);
    transpose_split2<<<dim3(DIM / 32, DIM / 32), tb>>>(Wv, wv0, wv1, DIM, DIM);

    // 2) fused [Q|K] = x @ [Wq|Wk]   (M=SEQ, N=2048) -> split planes, ldc=2048
    gemm_hmma<1><<<dim3(2 * DIM / 128, SEQ / 256), b256, GEMM_SMEM>>>(
        xp0, xp1, wqk0, wqk1, nullptr, qk0, qk1,
        2 * DIM, DIM, DIM, DIM, 2 * DIM, 1.0f);

    // 3) V^T = Wv^T @ x^T           (M=DIM, N=SEQ) -> split planes, ldc=SEQ
    gemm_hmma<1><<<dim3(SEQ / 128, DIM / 256), b256, GEMM_SMEM>>>(
        wv0, wv1, xp0, xp1, nullptr, vt0, vt1,
        SEQ, DIM, DIM, DIM, SEQ, 1.0f);

    // 4) scores S = (1/32) Q K^T    (A = Q cols of qk, B = K cols of qk)
    gemm_hmma<0><<<dim3(SEQ / 128, SEQ / 256), b256, GEMM_SMEM>>>(
        qk0, qk1, qk0 + DIM, qk1 + DIM, S, nullptr, nullptr,
        SEQ, DIM, 2 * DIM, 2 * DIM, SEQ, 0.03125f);

    // 5) softmax + split P
    softmax_split2<<<SEQ, b256>>>(S, pp0, pp1);

    // 6) out = P V                  (B = V^T planes, K-major over seq)
    gemm_hmma<0><<<dim3(DIM / 128, SEQ / 256), b256, GEMM_SMEM>>>(
        pp0, pp1, vt0, vt1, out, nullptr, nullptr,
        DIM, SEQ, SEQ, SEQ, DIM, 1.0f);
}

// round 8
// speedup vs baseline: 3.1370x; 1.0039x over previous
#include <cuda_runtime.h>
#include <cuda_fp16.h>
#include <stdint.h>
#include <math.h>

#define SEQ 4096
#define DIM 1024

typedef __half h16;

// ---------------- static device scratch ----------------
__device__ h16  g_xp[2][SEQ * DIM];                 // x split planes [SEQ, DIM]
__device__ h16  g_Wqkt[2][2 * DIM * DIM];           // [Wq^T ; Wk^T] planes [2048, 1024]
__device__ h16  g_Wvt[2][DIM * DIM];                // Wv^T planes [1024, 1024]
__device__ h16  g_QKp[2][(size_t)SEQ * 2 * DIM];    // [Q | K] planes [SEQ, 2048]
__device__ h16  g_Vt[2][(size_t)DIM * SEQ];         // V^T planes [DIM, SEQ]
__device__ float g_S[(size_t)SEQ * SEQ];
__device__ h16  g_Pp[2][(size_t)SEQ * SEQ];         // exp (unnormalized) planes
__device__ float g_inv[SEQ];                        // per-row 1/sum

// ---------------- helpers ----------------
__device__ __forceinline__ uint32_t smem_u32(const void* p) {
    uint32_t a;
    asm("{ .reg .u64 t; cvta.to.shared.u64 t, %1; cvt.u32.u64 %0, t; }" : "=r"(a) : "l"(p));
    return a;
}
__device__ __forceinline__ uint32_t sw128(uint32_t o) { return o ^ ((o >> 3) & 0x70); }

__device__ __forceinline__ void cp_async16(uint32_t s, const void* g) {
    asm volatile("cp.async.cg.shared.global [%0], [%1], 16;" :: "r"(s), "l"(g));
}
#define CP_COMMIT() asm volatile("cp.async.commit_group;" ::: "memory")
#define CP_WAIT1()  asm volatile("cp.async.wait_group 1;" ::: "memory")

__device__ __forceinline__ void ldsm4(uint32_t& r0, uint32_t& r1, uint32_t& r2, uint32_t& r3, uint32_t a) {
    asm volatile("ldmatrix.sync.aligned.m8n8.x4.shared.b16 {%0,%1,%2,%3}, [%4];"
                 : "=r"(r0), "=r"(r1), "=r"(r2), "=r"(r3) : "r"(a));
}
__device__ __forceinline__ void mma16816(float* c, const uint32_t* a, const uint32_t* b) {
    asm volatile("mma.sync.aligned.m16n8k16.row.col.f32.f16.f16.f32 "
                 "{%0,%1,%2,%3}, {%4,%5,%6,%7}, {%8,%9}, {%0,%1,%2,%3};"
                 : "+f"(c[0]), "+f"(c[1]), "+f"(c[2]), "+f"(c[3])
                 : "r"(a[0]), "r"(a[1]), "r"(a[2]), "r"(a[3]), "r"(b[0]), "r"(b[1]));
}
__device__ __forceinline__ void split2(float v, h16& x0, h16& x1) {
    x0 = __float2half_rn(v);
    x1 = __float2half_rn(v - __half2float(x0));
}

// ---------------------------------------------------------------------------
// HMMA GEMM:  C[M,N] = alpha * rowscale[m] * A[M,K] * B[N,K]^T  (K-major planes)
// 2-plane split, 3 products via K-segment concat: a0b0, a0b1, a1b0.
// CTA tile 256x128, BK=64, 8 warps (4x2 of 64x64), 3-stage cp.async pipeline.
// EPI=0: fp32 C; EPI=1: 2 fp16 split planes. rowscale==nullptr -> 1.0.
// ---------------------------------------------------------------------------
template <int EPI>
__global__ __launch_bounds__(256, 1) void gemm_hmma(
    const h16* __restrict__ a0, const h16* __restrict__ a1,
    const h16* __restrict__ b0, const h16* __restrict__ b1,
    float* __restrict__ C, h16* __restrict__ c0, h16* __restrict__ c1,
    const float* __restrict__ rowscale,
    int N, int Kd, int lda, int ldb, int ldc, float alpha)
{
    extern __shared__ char sm[];
    const uint32_t smu = smem_u32(sm);
    const int tid = threadIdx.x;
    const int wid = tid >> 5, lane = tid & 31;
    const int wm = wid >> 1, wn = wid & 1;            // 4x2 warp grid, 64x64 tiles
    const int row0 = blockIdx.y * 256, col0 = blockIdx.x * 128;

    const h16* segA[3] = {a0, a0, a1};
    const h16* segB[3] = {b0, b1, b0};
    const int cpk = Kd >> 6;
    const int nc = 3 * cpk;

    const int gr = tid >> 3;       // 0..31 base row
    const int gc = tid & 7;        // 16B granule in 128B row

    float acc[4][8][4];
#pragma unroll
    for (int i = 0; i < 4; i++)
#pragma unroll
        for (int j = 0; j < 8; j++)
#pragma unroll
            for (int q = 0; q < 4; q++) acc[i][j][q] = 0.0f;

    auto load_chunk = [&](int c, int b) {
        const int seg = c / cpk;
        const int kc = (c - seg * cpk) << 6;
        const h16* Ag = segA[seg];
        const h16* Bg = segB[seg];
        const uint32_t abase = smu + (uint32_t)b * 49152u;   // 48KB stage
        const uint32_t bbase = abase + 32768u;               // A:32KB, B:16KB
#pragma unroll
        for (int q = 0; q < 8; q++) {                        // A: 256 rows
            const int r = gr + q * 32;
            const uint32_t off = sw128((uint32_t)(r * 128 + gc * 16));
            cp_async16(abase + off, Ag + (size_t)(row0 + r) * lda + kc + gc * 8);
        }
#pragma unroll
        for (int q = 0; q < 4; q++) {                        // B: 128 rows
            const int r = gr + q * 32;
            const uint32_t off = sw128((uint32_t)(r * 128 + gc * 16));
            cp_async16(bbase + off, Bg + (size_t)(col0 + r) * ldb + kc + gc * 8);
        }
        CP_COMMIT();
    };

    // 3-stage pipeline: prologue loads chunks 0,1 into stages 0,1.
    load_chunk(0, 0);
    load_chunk(1, 1);

    int stage = 0;
    for (int c = 0; c < nc; c++) {
        CP_WAIT1();            // chunk c resident
        __syncthreads();       // all warps done with chunk c-1 -> its stage is free

        // issue next load BEFORE compute (into stage (c+2)%3 == the c-1 stage)
        if (c + 2 < nc) {
            int s2 = stage + 2; if (s2 >= 3) s2 -= 3;
            load_chunk(c + 2, s2);
        } else {
            CP_COMMIT();       // keep group accounting consistent
        }

        const uint32_t ab = smu + (uint32_t)stage * 49152u;
        const uint32_t bb = ab + 32768u;

#pragma unroll
        for (int ks = 0; ks < 4; ks++) {
            uint32_t af[4][4];
            uint32_t bf[8][2];
#pragma unroll
            for (int mt = 0; mt < 4; mt++) {
                const int rr = wm * 64 + mt * 16 + (lane & 15);
                const uint32_t off = sw128((uint32_t)(rr * 128 + ks * 32 + ((lane >> 4) << 4)));
                ldsm4(af[mt][0], af[mt][1], af[mt][2], af[mt][3], ab + off);
            }
#pragma unroll
            for (int nt2 = 0; nt2 < 4; nt2++) {
                const int nn = wn * 64 + nt2 * 16 + ((lane >> 4) << 3) + (lane & 7);
                const uint32_t off = sw128((uint32_t)(nn * 128 + ks * 32 + (((lane >> 3) & 1) << 4)));
                uint32_t r0, r1, r2, r3;
                ldsm4(r0, r1, r2, r3, bb + off);
                bf[nt2 * 2][0] = r0;     bf[nt2 * 2][1] = r1;
                bf[nt2 * 2 + 1][0] = r2; bf[nt2 * 2 + 1][1] = r3;
            }
#pragma unroll
            for (int mt = 0; mt < 4; mt++)
#pragma unroll
                for (int nt = 0; nt < 8; nt++)
                    mma16816(acc[mt][nt], af[mt], bf[nt]);
        }

        if (++stage == 3) stage = 0;
    }

    // ---- epilogue ----
    const int gid = lane >> 2, tig = lane & 3;
#pragma unroll
    for (int mt = 0; mt < 4; mt++) {
        const int r_ = row0 + wm * 64 + mt * 16 + gid;
        const float rs0 = alpha * (rowscale ? rowscale[r_] : 1.0f);
        const float rs1 = alpha * (rowscale ? rowscale[r_ + 8] : 1.0f);
#pragma unroll
        for (int nt = 0; nt < 8; nt++) {
            const int cc = col0 + wn * 64 + nt * 8 + tig * 2;
            const float v0 = rs0 * acc[mt][nt][0];
            const float v1 = rs0 * acc[mt][nt][1];
            const float v2 = rs1 * acc[mt][nt][2];
            const float v3 = rs1 * acc[mt][nt][3];
            if (EPI == 0) {
                *reinterpret_cast<float2*>(&C[(size_t)r_ * ldc + cc]) = make_float2(v0, v1);
                *reinterpret_cast<float2*>(&C[(size_t)(r_ + 8) * ldc + cc]) = make_float2(v2, v3);
            } else {
                h16 p0, p1, q0, q1;
                split2(v0, p0, p1); split2(v1, q0, q1);
                __half2 lo0; lo0.x = p0; lo0.y = q0;
                __half2 lo1; lo1.x = p1; lo1.y = q1;
                *reinterpret_cast<__half2*>(c0 + (size_t)r_ * ldc + cc) = lo0;
                *reinterpret_cast<__half2*>(c1 + (size_t)r_ * ldc + cc) = lo1;
                split2(v2, p0, p1); split2(v3, q0, q1);
                __half2 hi0; hi0.x = p0; hi0.y = q0;
                __half2 hi1; hi1.x = p1; hi1.y = q1;
                *reinterpret_cast<__half2*>(c0 + (size_t)(r_ + 8) * ldc + cc) = hi0;
                *reinterpret_cast<__half2*>(c1 + (size_t)(r_ + 8) * ldc + cc) = hi1;
            }
        }
    }
}

#define GEMM_SMEM 147456

// ---------------------------------------------------------------------------
__global__ __launch_bounds__(256) void split_planes2(
    const float* __restrict__ src, h16* __restrict__ d0, h16* __restrict__ d1, int n)
{
    int i = (blockIdx.x * 256 + threadIdx.x) * 2;
    if (i < n) {
        float2 v = *reinterpret_cast<const float2*>(src + i);
        h16 a0, a1, b0, b1;
        split2(v.x, a0, a1); split2(v.y, b0, b1);
        __half2 p0; p0.x = a0; p0.y = b0;
        __half2 p1; p1.x = a1; p1.y = b1;
        *reinterpret_cast<__half2*>(d0 + i) = p0;
        *reinterpret_cast<__half2*>(d1 + i) = p1;
    }
}

// fp32 [R,C] -> transposed 2 fp16 planes [C,R]
__global__ __launch_bounds__(256) void transpose_split2(
    const float* __restrict__ src, h16* __restrict__ d0, h16* __restrict__ d1, int R, int C)
{
    __shared__ float t[32][33];
    const int tx = threadIdx.x, ty = threadIdx.y;
    const int r0 = blockIdx.y * 32, c0 = blockIdx.x * 32;
#pragma unroll
    for (int j = 0; j < 32; j += 8)
        t[ty + j][tx] = src[(size_t)(r0 + ty + j) * C + c0 + tx];
    __syncthreads();
#pragma unroll
    for (int j = 0; j < 32; j += 8) {
        float v = t[tx][ty + j];
        h16 h0, h1;
        split2(v, h0, h1);
        size_t o = (size_t)(c0 + ty + j) * R + r0 + tx;
        d0[o] = h0; d1[o] = h1;
    }
}

// ---------------------------------------------------------------------------
// Row softmax (unnormalized): P = exp(s - rowmax) as 2 fp16 planes,
// inv[row] = 1/sum. Normalization folded into PV epilogue.
// ---------------------------------------------------------------------------
__global__ __launch_bounds__(256) void softmax_exp_split2(
    const float* __restrict__ S, h16* __restrict__ P0, h16* __restrict__ P1,
    float* __restrict__ inv)
{
    const int row = blockIdx.x;
    const float* p = S + (size_t)row * SEQ;
    const int tid = threadIdx.x;
    __shared__ float red[256];

    float mx = -INFINITY;
    for (int i = tid; i < SEQ; i += 256) mx = fmaxf(mx, p[i]);
    red[tid] = mx;
    __syncthreads();
#pragma unroll
    for (int s = 128; s > 0; s >>= 1) {
        if (tid < s) red[tid] = fmaxf(red[tid], red[tid + s]);
        __syncthreads();
    }
    mx = red[0];
    __syncthreads();

    const size_t base = (size_t)row * SEQ;
    float sum = 0.0f;
    for (int i = tid * 2; i < SEQ; i += 512) {
        float2 v = *reinterpret_cast<const float2*>(p + i);
        float e0 = expf(v.x - mx);
        float e1 = expf(v.y - mx);
        sum += e0 + e1;
        h16 a0, a1, b0, b1;
        split2(e0, a0, a1); split2(e1, b0, b1);
        __half2 q0; q0.x = a0; q0.y = b0;
        __half2 q1; q1.x = a1; q1.y = b1;
        *reinterpret_cast<__half2*>(P0 + base + i) = q0;
        *reinterpret_cast<__half2*>(P1 + base + i) = q1;
    }
    red[tid] = sum;
    __syncthreads();
#pragma unroll
    for (int s = 128; s > 0; s >>= 1) {
        if (tid < s) red[tid] += red[tid + s];
        __syncthreads();
    }
    if (tid == 0) inv[row] = 1.0f / red[0];
}

// ---------------------------------------------------------------------------
extern "C" void kernel_launch(void* const* d_in, const int* in_sizes, int n_in,
                              void* d_out, int out_size)
{
    const float* x  = (const float*)d_in[0];
    const float* Wq = (const float*)d_in[1];
    const float* Wk = (const float*)d_in[2];
    const float* Wv = (const float*)d_in[3];
    float* out = (float*)d_out;

    h16 *xp, *wqkt, *wvt, *qkp, *vt, *pp;
    float *S, *inv;
    cudaGetSymbolAddress((void**)&xp,   g_xp);
    cudaGetSymbolAddress((void**)&wqkt, g_Wqkt);
    cudaGetSymbolAddress((void**)&wvt,  g_Wvt);
    cudaGetSymbolAddress((void**)&qkp,  g_QKp);
    cudaGetSymbolAddress((void**)&vt,   g_Vt);
    cudaGetSymbolAddress((void**)&S,    g_S);
    cudaGetSymbolAddress((void**)&pp,   g_Pp);
    cudaGetSymbolAddress((void**)&inv,  g_inv);

    const size_t ND = (size_t)SEQ * DIM;      // 4M
    const size_t DD = (size_t)DIM * DIM;      // 1M
    const size_t N2 = (size_t)SEQ * 2 * DIM;  // 8M
    const size_t NN = (size_t)SEQ * SEQ;      // 16M

    h16 *xp0 = xp, *xp1 = xp + ND;
    h16 *wqk0 = wqkt, *wqk1 = wqkt + 2 * DD;
    h16 *wv0 = wvt, *wv1 = wvt + DD;
    h16 *qk0 = qkp, *qk1 = qkp + N2;
    h16 *vt0 = vt, *vt1 = vt + ND;
    h16 *pp0 = pp, *pp1 = pp + NN;

    cudaFuncSetAttribute(gemm_hmma<0>, cudaFuncAttributeMaxDynamicSharedMemorySize, GEMM_SMEM);
    cudaFuncSetAttribute(gemm_hmma<1>, cudaFuncAttributeMaxDynamicSharedMemorySize, GEMM_SMEM);

    dim3 b256(256);
    dim3 tb(32, 8);

    // 1) split x; transpose-split weights (Wq,Wk fused into one [2048,1024] buffer)
    split_planes2<<<(int)(ND / 512), b256>>>(x, xp0, xp1, (int)ND);
    transpose_split2<<<dim3(DIM / 32, DIM / 32), tb>>>(Wq, wqk0, wqk1, DIM, DIM);
    transpose_split2<<<dim3(DIM / 32, DIM / 32), tb>>>(Wk, wqk0 + DD, wqk1 + DD, DIM, DIM);
    transpose_split2<<<dim3(DIM / 32, DIM / 32), tb>>>(Wv, wv0, wv1, DIM, DIM);

    // 2) fused [Q|K] = x @ [Wq|Wk]   (M=SEQ, N=2048) -> split planes, ldc=2048
    gemm_hmma<1><<<dim3(2 * DIM / 128, SEQ / 256), b256, GEMM_SMEM>>>(
        xp0, xp1, wqk0, wqk1, nullptr, qk0, qk1, nullptr,
        2 * DIM, DIM, DIM, DIM, 2 * DIM, 1.0f);

    // 3) V^T = Wv^T @ x^T           (M=DIM, N=SEQ) -> split planes, ldc=SEQ
    gemm_hmma<1><<<dim3(SEQ / 128, DIM / 256), b256, GEMM_SMEM>>>(
        wv0, wv1, xp0, xp1, nullptr, vt0, vt1, nullptr,
        SEQ, DIM, DIM, DIM, SEQ, 1.0f);

    // 4) scores S = (1/32) Q K^T
    gemm_hmma<0><<<dim3(SEQ / 128, SEQ / 256), b256, GEMM_SMEM>>>(
        qk0, qk1, qk0 + DIM, qk1 + DIM, S, nullptr, nullptr, nullptr,
        SEQ, DIM, 2 * DIM, 2 * DIM, SEQ, 0.03125f);

    // 5) softmax: unnormalized exp planes + 1/sum
    softmax_exp_split2<<<SEQ, b256>>>(S, pp0, pp1, inv);

    // 6) out = diag(inv) * P V      (normalization folded into epilogue)
    gemm_hmma<0><<<dim3(DIM / 128, SEQ / 256), b256, GEMM_SMEM>>>(
        pp0, pp1, vt0, vt1, out, nullptr, nullptr, inv,
        DIM, SEQ, SEQ, SEQ, DIM, 1.0f);
}

// round 10
// speedup vs baseline: 3.5201x; 1.1221x over previous
#include <cuda_runtime.h>
#include <cuda_fp16.h>
#include <stdint.h>
#include <math.h>

#define SEQ 4096
#define DIM 1024

typedef __half h16;

// ---------------- static device scratch ----------------
__device__ h16  g_xp[2][SEQ * DIM];                 // x split planes [SEQ, DIM]
__device__ h16  g_Wqkt[2][2 * DIM * DIM];           // [Wq^T ; Wk^T] planes [2048, 1024]
__device__ h16  g_Wvt[2][DIM * DIM];                // Wv^T planes [1024, 1024]
__device__ h16  g_QKp[2][(size_t)SEQ * 2 * DIM];    // [Q | K] planes [SEQ, 2048]
__device__ h16  g_Vt[(size_t)DIM * SEQ];            // V^T single fp16 plane [DIM, SEQ]
__device__ float g_S[(size_t)SEQ * SEQ];
__device__ h16  g_Pp[2][(size_t)SEQ * SEQ];         // exp (unnormalized) planes
__device__ float g_inv[SEQ];                        // per-row 1/sum

// ---------------- helpers ----------------
__device__ __forceinline__ uint32_t smem_u32(const void* p) {
    uint32_t a;
    asm("{ .reg .u64 t; cvta.to.shared.u64 t, %1; cvt.u32.u64 %0, t; }" : "=r"(a) : "l"(p));
    return a;
}
__device__ __forceinline__ uint32_t sw128(uint32_t o) { return o ^ ((o >> 3) & 0x70); }

__device__ __forceinline__ void cp_async16(uint32_t s, const void* g) {
    asm volatile("cp.async.cg.shared.global [%0], [%1], 16;" :: "r"(s), "l"(g));
}
#define CP_COMMIT() asm volatile("cp.async.commit_group;" ::: "memory")
#define CP_WAIT1()  asm volatile("cp.async.wait_group 1;" ::: "memory")

__device__ __forceinline__ void ldsm4(uint32_t& r0, uint32_t& r1, uint32_t& r2, uint32_t& r3, uint32_t a) {
    asm volatile("ldmatrix.sync.aligned.m8n8.x4.shared.b16 {%0,%1,%2,%3}, [%4];"
                 : "=r"(r0), "=r"(r1), "=r"(r2), "=r"(r3) : "r"(a));
}
__device__ __forceinline__ void mma16816(float* c, const uint32_t* a, const uint32_t* b) {
    asm volatile("mma.sync.aligned.m16n8k16.row.col.f32.f16.f16.f32 "
                 "{%0,%1,%2,%3}, {%4,%5,%6,%7}, {%8,%9}, {%0,%1,%2,%3};"
                 : "+f"(c[0]), "+f"(c[1]), "+f"(c[2]), "+f"(c[3])
                 : "r"(a[0]), "r"(a[1]), "r"(a[2]), "r"(a[3]), "r"(b[0]), "r"(b[1]));
}
__device__ __forceinline__ void split2(float v, h16& x0, h16& x1) {
    x0 = __float2half_rn(v);
    x1 = __float2half_rn(v - __half2float(x0));
}

// ---------------------------------------------------------------------------
// HMMA GEMM:  C[M,N] = alpha * rowscale[m] * A[M,K] * B[N,K]^T  (K-major planes)
// NSEG=3: products a0b0 + a0b1 + a1b0 (full split)
// NSEG=2: products a0b0 + a1b0     (A 2-plane x B single-plane)
// CTA tile 256x128, BK=64, 8 warps (4x2 of 64x64), 3-stage cp.async pipeline.
// EPI=0: fp32 C. EPI=1: 2 fp16 split planes. EPI=2: single fp16 plane.
// ---------------------------------------------------------------------------
template <int EPI, int NSEG>
__global__ __launch_bounds__(256, 1) void gemm_hmma(
    const h16* __restrict__ a0, const h16* __restrict__ a1,
    const h16* __restrict__ b0, const h16* __restrict__ b1,
    float* __restrict__ C, h16* __restrict__ c0, h16* __restrict__ c1,
    const float* __restrict__ rowscale,
    int N, int Kd, int lda, int ldb, int ldc, float alpha)
{
    extern __shared__ char sm[];
    const uint32_t smu = smem_u32(sm);
    const int tid = threadIdx.x;
    const int wid = tid >> 5, lane = tid & 31;
    const int wm = wid >> 1, wn = wid & 1;            // 4x2 warp grid, 64x64 tiles
    const int row0 = blockIdx.y * 256, col0 = blockIdx.x * 128;

    const h16* segA[3];
    const h16* segB[3];
    if (NSEG == 3) {
        segA[0] = a0; segA[1] = a0; segA[2] = a1;
        segB[0] = b0; segB[1] = b1; segB[2] = b0;
    } else {
        segA[0] = a0; segA[1] = a1; segA[2] = a1;
        segB[0] = b0; segB[1] = b0; segB[2] = b0;
    }
    const int cpk = Kd >> 6;
    const int nc = NSEG * cpk;

    const int gr = tid >> 3;       // 0..31 base row
    const int gc = tid & 7;        // 16B granule in 128B row

    float acc[4][8][4];
#pragma unroll
    for (int i = 0; i < 4; i++)
#pragma unroll
        for (int j = 0; j < 8; j++)
#pragma unroll
            for (int q = 0; q < 4; q++) acc[i][j][q] = 0.0f;

    auto load_chunk = [&](int c, int b) {
        const int seg = c / cpk;
        const int kc = (c - seg * cpk) << 6;
        const h16* Ag = segA[seg];
        const h16* Bg = segB[seg];
        const uint32_t abase = smu + (uint32_t)b * 49152u;   // 48KB stage
        const uint32_t bbase = abase + 32768u;               // A:32KB, B:16KB
#pragma unroll
        for (int q = 0; q < 8; q++) {                        // A: 256 rows
            const int r = gr + q * 32;
            const uint32_t off = sw128((uint32_t)(r * 128 + gc * 16));
            cp_async16(abase + off, Ag + (size_t)(row0 + r) * lda + kc + gc * 8);
        }
#pragma unroll
        for (int q = 0; q < 4; q++) {                        // B: 128 rows
            const int r = gr + q * 32;
            const uint32_t off = sw128((uint32_t)(r * 128 + gc * 16));
            cp_async16(bbase + off, Bg + (size_t)(col0 + r) * ldb + kc + gc * 8);
        }
        CP_COMMIT();
    };

    load_chunk(0, 0);
    load_chunk(1, 1);

    int stage = 0;
    for (int c = 0; c < nc; c++) {
        CP_WAIT1();            // chunk c resident
        __syncthreads();       // chunk c-1 consumers done -> its stage is free

        if (c + 2 < nc) {
            int s2 = stage + 2; if (s2 >= 3) s2 -= 3;
            load_chunk(c + 2, s2);
        } else {
            CP_COMMIT();
        }

        const uint32_t ab = smu + (uint32_t)stage * 49152u;
        const uint32_t bb = ab + 32768u;

#pragma unroll
        for (int ks = 0; ks < 4; ks++) {
            uint32_t af[4][4];
            uint32_t bf[8][2];
#pragma unroll
            for (int mt = 0; mt < 4; mt++) {
                const int rr = wm * 64 + mt * 16 + (lane & 15);
                const uint32_t off = sw128((uint32_t)(rr * 128 + ks * 32 + ((lane >> 4) << 4)));
                ldsm4(af[mt][0], af[mt][1], af[mt][2], af[mt][3], ab + off);
            }
#pragma unroll
            for (int nt2 = 0; nt2 < 4; nt2++) {
                const int nn = wn * 64 + nt2 * 16 + ((lane >> 4) << 3) + (lane & 7);
                const uint32_t off = sw128((uint32_t)(nn * 128 + ks * 32 + (((lane >> 3) & 1) << 4)));
                uint32_t r0, r1, r2, r3;
                ldsm4(r0, r1, r2, r3, bb + off);
                bf[nt2 * 2][0] = r0;     bf[nt2 * 2][1] = r1;
                bf[nt2 * 2 + 1][0] = r2; bf[nt2 * 2 + 1][1] = r3;
            }
#pragma unroll
            for (int mt = 0; mt < 4; mt++)
#pragma unroll
                for (int nt = 0; nt < 8; nt++)
                    mma16816(acc[mt][nt], af[mt], bf[nt]);
        }

        if (++stage == 3) stage = 0;
    }

    // ---- epilogue ----
    const int gid = lane >> 2, tig = lane & 3;
#pragma unroll
    for (int mt = 0; mt < 4; mt++) {
        const int r_ = row0 + wm * 64 + mt * 16 + gid;
        const float rs0 = alpha * (rowscale ? rowscale[r_] : 1.0f);
        const float rs1 = alpha * (rowscale ? rowscale[r_ + 8] : 1.0f);
#pragma unroll
        for (int nt = 0; nt < 8; nt++) {
            const int cc = col0 + wn * 64 + nt * 8 + tig * 2;
            const float v0 = rs0 * acc[mt][nt][0];
            const float v1 = rs0 * acc[mt][nt][1];
            const float v2 = rs1 * acc[mt][nt][2];
            const float v3 = rs1 * acc[mt][nt][3];
            if (EPI == 0) {
                *reinterpret_cast<float2*>(&C[(size_t)r_ * ldc + cc]) = make_float2(v0, v1);
                *reinterpret_cast<float2*>(&C[(size_t)(r_ + 8) * ldc + cc]) = make_float2(v2, v3);
            } else if (EPI == 1) {
                h16 p0, p1, q0, q1;
                split2(v0, p0, p1); split2(v1, q0, q1);
                __half2 lo0; lo0.x = p0; lo0.y = q0;
                __half2 lo1; lo1.x = p1; lo1.y = q1;
                *reinterpret_cast<__half2*>(c0 + (size_t)r_ * ldc + cc) = lo0;
                *reinterpret_cast<__half2*>(c1 + (size_t)r_ * ldc + cc) = lo1;
                split2(v2, p0, p1); split2(v3, q0, q1);
                __half2 hi0; hi0.x = p0; hi0.y = q0;
                __half2 hi1; hi1.x = p1; hi1.y = q1;
                *reinterpret_cast<__half2*>(c0 + (size_t)(r_ + 8) * ldc + cc) = hi0;
                *reinterpret_cast<__half2*>(c1 + (size_t)(r_ + 8) * ldc + cc) = hi1;
            } else {
                __half2 lo; lo.x = __float2half_rn(v0); lo.y = __float2half_rn(v1);
                __half2 hi; hi.x = __float2half_rn(v2); hi.y = __float2half_rn(v3);
                *reinterpret_cast<__half2*>(c0 + (size_t)r_ * ldc + cc) = lo;
                *reinterpret_cast<__half2*>(c0 + (size_t)(r_ + 8) * ldc + cc) = hi;
            }
        }
    }
}

#define GEMM_SMEM 147456

// ---------------------------------------------------------------------------
__global__ __launch_bounds__(256) void split_planes2(
    const float* __restrict__ src, h16* __restrict__ d0, h16* __restrict__ d1, int n)
{
    int i = (blockIdx.x * 256 + threadIdx.x) * 2;
    if (i < n) {
        float2 v = *reinterpret_cast<const float2*>(src + i);
        h16 a0, a1, b0, b1;
        split2(v.x, a0, a1); split2(v.y, b0, b1);
        __half2 p0; p0.x = a0; p0.y = b0;
        __half2 p1; p1.x = a1; p1.y = b1;
        *reinterpret_cast<__half2*>(d0 + i) = p0;
        *reinterpret_cast<__half2*>(d1 + i) = p1;
    }
}

// fp32 [R,C] -> transposed 2 fp16 planes [C,R]; blockIdx.z selects src/dst pair
__global__ __launch_bounds__(256) void transpose_split2_dual(
    const float* __restrict__ srcA, const float* __restrict__ srcB,
    h16* __restrict__ d0, h16* __restrict__ d1, int R, int C, size_t dstStride)
{
    __shared__ float t[32][33];
    const float* src = (blockIdx.z == 0) ? srcA : srcB;
    h16* e0 = d0 + (size_t)blockIdx.z * dstStride;
    h16* e1 = d1 + (size_t)blockIdx.z * dstStride;
    const int tx = threadIdx.x, ty = threadIdx.y;
    const int r0 = blockIdx.y * 32, c0 = blockIdx.x * 32;
#pragma unroll
    for (int j = 0; j < 32; j += 8)
        t[ty + j][tx] = src[(size_t)(r0 + ty + j) * C + c0 + tx];
    __syncthreads();
#pragma unroll
    for (int j = 0; j < 32; j += 8) {
        float v = t[tx][ty + j];
        h16 h0, h1;
        split2(v, h0, h1);
        size_t o = (size_t)(c0 + ty + j) * R + r0 + tx;
        e0[o] = h0; e1[o] = h1;
    }
}

// ---------------------------------------------------------------------------
// Row softmax (unnormalized): P = exp(s - rowmax) as 2 fp16 planes,
// inv[row] = 1/sum. Normalization folded into PV epilogue.
// ---------------------------------------------------------------------------
__global__ __launch_bounds__(256) void softmax_exp_split2(
    const float* __restrict__ S, h16* __restrict__ P0, h16* __restrict__ P1,
    float* __restrict__ inv)
{
    const int row = blockIdx.x;
    const float* p = S + (size_t)row * SEQ;
    const int tid = threadIdx.x;
    __shared__ float red[256];

    float mx = -INFINITY;
    for (int i = tid; i < SEQ; i += 256) mx = fmaxf(mx, p[i]);
    red[tid] = mx;
    __syncthreads();
#pragma unroll
    for (int s = 128; s > 0; s >>= 1) {
        if (tid < s) red[tid] = fmaxf(red[tid], red[tid + s]);
        __syncthreads();
    }
    mx = red[0];
    __syncthreads();

    const size_t base = (size_t)row * SEQ;
    float sum = 0.0f;
    for (int i = tid * 2; i < SEQ; i += 512) {
        float2 v = *reinterpret_cast<const float2*>(p + i);
        float e0 = expf(v.x - mx);
        float e1 = expf(v.y - mx);
        sum += e0 + e1;
        h16 a0, a1, b0, b1;
        split2(e0, a0, a1); split2(e1, b0, b1);
        __half2 q0; q0.x = a0; q0.y = b0;
        __half2 q1; q1.x = a1; q1.y = b1;
        *reinterpret_cast<__half2*>(P0 + base + i) = q0;
        *reinterpret_cast<__half2*>(P1 + base + i) = q1;
    }
    red[tid] = sum;
    __syncthreads();
#pragma unroll
    for (int s = 128; s > 0; s >>= 1) {
        if (tid < s) red[tid] += red[tid + s];
        __syncthreads();
    }
    if (tid == 0) inv[row] = 1.0f / red[0];
}

// ---------------------------------------------------------------------------
extern "C" void kernel_launch(void* const* d_in, const int* in_sizes, int n_in,
                              void* d_out, int out_size)
{
    const float* x  = (const float*)d_in[0];
    const float* Wq = (const float*)d_in[1];
    const float* Wk = (const float*)d_in[2];
    const float* Wv = (const float*)d_in[3];
    float* out = (float*)d_out;

    h16 *xp, *wqkt, *wvt, *qkp, *vt, *pp;
    float *S, *inv;
    cudaGetSymbolAddress((void**)&xp,   g_xp);
    cudaGetSymbolAddress((void**)&wqkt, g_Wqkt);
    cudaGetSymbolAddress((void**)&wvt,  g_Wvt);
    cudaGetSymbolAddress((void**)&qkp,  g_QKp);
    cudaGetSymbolAddress((void**)&vt,   g_Vt);
    cudaGetSymbolAddress((void**)&S,    g_S);
    cudaGetSymbolAddress((void**)&pp,   g_Pp);
    cudaGetSymbolAddress((void**)&inv,  g_inv);

    const size_t ND = (size_t)SEQ * DIM;      // 4M
    const size_t DD = (size_t)DIM * DIM;      // 1M
    const size_t N2 = (size_t)SEQ * 2 * DIM;  // 8M
    const size_t NN = (size_t)SEQ * SEQ;      // 16M

    h16 *xp0 = xp, *xp1 = xp + ND;
    h16 *wqk0 = wqkt, *wqk1 = wqkt + 2 * DD;
    h16 *wv0 = wvt, *wv1 = wvt + DD;
    h16 *qk0 = qkp, *qk1 = qkp + N2;
    h16 *pp0 = pp, *pp1 = pp + NN;

    cudaFuncSetAttribute((const void*)gemm_hmma<0, 3>, cudaFuncAttributeMaxDynamicSharedMemorySize, GEMM_SMEM);
    cudaFuncSetAttribute((const void*)gemm_hmma<1, 3>, cudaFuncAttributeMaxDynamicSharedMemorySize, GEMM_SMEM);
    cudaFuncSetAttribute((const void*)gemm_hmma<2, 3>, cudaFuncAttributeMaxDynamicSharedMemorySize, GEMM_SMEM);
    cudaFuncSetAttribute((const void*)gemm_hmma<0, 2>, cudaFuncAttributeMaxDynamicSharedMemorySize, GEMM_SMEM);

    dim3 b256(256);
    dim3 tb(32, 8);

    // 1) split x
    split_planes2<<<(int)(ND / 512), b256>>>(x, xp0, xp1, (int)ND);

    // 2) fused Wq+Wk transpose (one launch, z=2)
    transpose_split2_dual<<<dim3(DIM / 32, DIM / 32, 2), tb>>>(
        Wq, Wk, wqk0, wqk1, DIM, DIM, DD);

    // 3) fused [Q|K] = x @ [Wq|Wk]   (M=SEQ, N=2048), split planes, ldc=2048
    gemm_hmma<1, 3><<<dim3(2 * DIM / 128, SEQ / 256), b256, GEMM_SMEM>>>(
        xp0, xp1, wqk0, wqk1, nullptr, qk0, qk1, nullptr,
        2 * DIM, DIM, DIM, DIM, 2 * DIM, 1.0f);

    // 4) scores S = (1/32) Q K^T    (full 3-product accuracy)
    gemm_hmma<0, 3><<<dim3(SEQ / 128, SEQ / 256), b256, GEMM_SMEM>>>(
        qk0, qk1, qk0 + DIM, qk1 + DIM, S, nullptr, nullptr, nullptr,
        SEQ, DIM, 2 * DIM, 2 * DIM, SEQ, 0.03125f);

    // 5) Wv transpose-split
    transpose_split2_dual<<<dim3(DIM / 32, DIM / 32, 1), tb>>>(
        Wv, Wv, wv0, wv1, DIM, DIM, 0);

    // 6) V^T = Wv^T @ x^T (M=DIM, N=SEQ), single fp16 plane output, ldc=SEQ
    gemm_hmma<2, 3><<<dim3(SEQ / 128, DIM / 256), b256, GEMM_SMEM>>>(
        wv0, wv1, xp0, xp1, nullptr, vt, nullptr, nullptr,
        SEQ, DIM, DIM, DIM, SEQ, 1.0f);

    // 7) softmax: unnormalized exp planes + 1/sum
    softmax_exp_split2<<<SEQ, b256>>>(S, pp0, pp1, inv);

    // 8) out = diag(inv) * P V   (2 products: p0*v + p1*v; V single plane)
    gemm_hmma<0, 2><<<dim3(DIM / 128, SEQ / 256), b256, GEMM_SMEM>>>(
        pp0, pp1, vt, nullptr, out, nullptr, nullptr, inv,
        DIM, SEQ, SEQ, SEQ, DIM, 1.0f);
}

// round 12
// speedup vs baseline: 3.7614x; 1.0686x over previous
#include <cuda_runtime.h>
#include <cuda_fp16.h>
#include <stdint.h>
#include <math.h>

#define SEQ 4096
#define DIM 1024

typedef __half h16;

// ---------------- static device scratch ----------------
__device__ h16  g_xp[2][SEQ * DIM];                 // x split planes [SEQ, DIM]
__device__ h16  g_Wqkt[2][2 * DIM * DIM];           // [Wq^T ; Wk^T] planes [2048, 1024]
__device__ h16  g_Wvt[2][DIM * DIM];                // Wv^T planes [1024, 1024]
__device__ h16  g_QKp[2][(size_t)SEQ * 2 * DIM];    // [Q | K] planes [SEQ, 2048]
__device__ h16  g_Vt[(size_t)DIM * SEQ];            // V^T single fp16 plane [DIM, SEQ]
__device__ float g_S[(size_t)SEQ * SEQ];
__device__ h16  g_Pp[2][(size_t)SEQ * SEQ];         // exp (unnormalized) planes
__device__ float g_inv[SEQ];                        // per-row 1/sum

// ---------------- helpers ----------------
__device__ __forceinline__ uint32_t smem_u32(const void* p) {
    uint32_t a;
    asm("{ .reg .u64 t; cvta.to.shared.u64 t, %1; cvt.u32.u64 %0, t; }" : "=r"(a) : "l"(p));
    return a;
}
__device__ __forceinline__ uint32_t sw128(uint32_t o) { return o ^ ((o >> 3) & 0x70); }

__device__ __forceinline__ void cp_async16(uint32_t s, const void* g) {
    asm volatile("cp.async.cg.shared.global [%0], [%1], 16;" :: "r"(s), "l"(g));
}
#define CP_COMMIT() asm volatile("cp.async.commit_group;" ::: "memory")
#define CP_WAIT1()  asm volatile("cp.async.wait_group 1;" ::: "memory")

__device__ __forceinline__ void ldsm4(uint32_t& r0, uint32_t& r1, uint32_t& r2, uint32_t& r3, uint32_t a) {
    asm volatile("ldmatrix.sync.aligned.m8n8.x4.shared.b16 {%0,%1,%2,%3}, [%4];"
                 : "=r"(r0), "=r"(r1), "=r"(r2), "=r"(r3) : "r"(a));
}
__device__ __forceinline__ void mma16816(float* c, const uint32_t* a, const uint32_t* b) {
    asm volatile("mma.sync.aligned.m16n8k16.row.col.f32.f16.f16.f32 "
                 "{%0,%1,%2,%3}, {%4,%5,%6,%7}, {%8,%9}, {%0,%1,%2,%3};"
                 : "+f"(c[0]), "+f"(c[1]), "+f"(c[2]), "+f"(c[3])
                 : "r"(a[0]), "r"(a[1]), "r"(a[2]), "r"(a[3]), "r"(b[0]), "r"(b[1]));
}
__device__ __forceinline__ void split2(float v, h16& x0, h16& x1) {
    x0 = __float2half_rn(v);
    x1 = __float2half_rn(v - __half2float(x0));
}

// ---------------------------------------------------------------------------
// GEMM body:  C[M,N] = alpha * rowscale[m] * A[M,K] * B[N,K]^T  (K-major planes)
// NSEG=3: a0b0 + a0b1 + a1b0.  NSEG=2: a0b0 + a1b0 (B single plane).
// CTA tile 256x128, BK=64, 8 warps (4x2 of 64x64), 3-stage cp.async pipeline,
// register double-buffered ldmatrix fragments (ks-level software pipeline).
// EPI=0: fp32 C. EPI=1: 2 fp16 split planes. EPI=2: single fp16 plane.
// ---------------------------------------------------------------------------
template <int EPI, int NSEG>
__device__ __forceinline__ void gemm_body(
    int bx, int by, char* sm,
    const h16* __restrict__ a0, const h16* __restrict__ a1,
    const h16* __restrict__ b0, const h16* __restrict__ b1,
    float* __restrict__ C, h16* __restrict__ c0, h16* __restrict__ c1,
    const float* __restrict__ rowscale,
    int N, int Kd, int lda, int ldb, int ldc, float alpha)
{
    const uint32_t smu = smem_u32(sm);
    const int tid = threadIdx.x;
    const int wid = tid >> 5, lane = tid & 31;
    const int wm = wid >> 1, wn = wid & 1;            // 4x2 warp grid, 64x64 tiles
    const int row0 = by * 256, col0 = bx * 128;

    const h16* segA[3];
    const h16* segB[3];
    if (NSEG == 3) {
        segA[0] = a0; segA[1] = a0; segA[2] = a1;
        segB[0] = b0; segB[1] = b1; segB[2] = b0;
    } else {
        segA[0] = a0; segA[1] = a1; segA[2] = a1;
        segB[0] = b0; segB[1] = b0; segB[2] = b0;
    }
    const int cpk = Kd >> 6;
    const int nc = NSEG * cpk;

    const int gr = tid >> 3;       // 0..31 base row
    const int gc = tid & 7;        // 16B granule in 128B row

    float acc[4][8][4];
#pragma unroll
    for (int i = 0; i < 4; i++)
#pragma unroll
        for (int j = 0; j < 8; j++)
#pragma unroll
            for (int q = 0; q < 4; q++) acc[i][j][q] = 0.0f;

    // precomputed fragment smem offsets (swizzle-dependent on lane only)
    const int arr = wm * 64 + (lane & 15);
    const uint32_t abase_lane = (uint32_t)(arr * 128 + ((lane >> 4) << 4));
    const int bnn = wn * 64 + ((lane >> 4) << 3) + (lane & 7);
    const uint32_t bbase_lane = (uint32_t)(bnn * 128 + (((lane >> 3) & 1) << 4));

    auto load_chunk = [&](int c, int b) {
        const int seg = c / cpk;
        const int kc = (c - seg * cpk) << 6;
        const h16* Ag = segA[seg];
        const h16* Bg = segB[seg];
        const uint32_t ab = smu + (uint32_t)b * 49152u;     // 48KB stage
        const uint32_t bb = ab + 32768u;                    // A:32KB, B:16KB
#pragma unroll
        for (int q = 0; q < 8; q++) {
            const int r = gr + q * 32;
            const uint32_t off = sw128((uint32_t)(r * 128 + gc * 16));
            cp_async16(ab + off, Ag + (size_t)(row0 + r) * lda + kc + gc * 8);
        }
#pragma unroll
        for (int q = 0; q < 4; q++) {
            const int r = gr + q * 32;
            const uint32_t off = sw128((uint32_t)(r * 128 + gc * 16));
            cp_async16(bb + off, Bg + (size_t)(col0 + r) * ldb + kc + gc * 8);
        }
        CP_COMMIT();
    };

    load_chunk(0, 0);
    load_chunk(1, 1);

    uint32_t af[2][4][4];
    uint32_t bf[2][8][2];

    auto ld_frags = [&](uint32_t ab, uint32_t bb, int ks, int buf) {
#pragma unroll
        for (int mt = 0; mt < 4; mt++) {
            const uint32_t off = sw128(abase_lane + (uint32_t)(mt * 16 * 128 + ks * 32));
            ldsm4(af[buf][mt][0], af[buf][mt][1], af[buf][mt][2], af[buf][mt][3], ab + off);
        }
#pragma unroll
        for (int nt2 = 0; nt2 < 4; nt2++) {
            const uint32_t off = sw128(bbase_lane + (uint32_t)(nt2 * 16 * 128 + ks * 32));
            uint32_t r0, r1, r2, r3;
            ldsm4(r0, r1, r2, r3, bb + off);
            bf[buf][nt2 * 2][0] = r0;     bf[buf][nt2 * 2][1] = r1;
            bf[buf][nt2 * 2 + 1][0] = r2; bf[buf][nt2 * 2 + 1][1] = r3;
        }
    };

    int stage = 0;
    for (int c = 0; c < nc; c++) {
        CP_WAIT1();            // chunk c resident
        __syncthreads();       // chunk c-1 consumers done -> its stage is free

        const uint32_t ab = smu + (uint32_t)stage * 49152u;
        const uint32_t bb = ab + 32768u;

        // load first fragments so MMAs can start immediately
        ld_frags(ab, bb, 0, 0);

        // issue next chunk's cp.async (into the stage freed by iter c-1)
        if (c + 2 < nc) {
            int s2 = stage + 2; if (s2 >= 3) s2 -= 3;
            load_chunk(c + 2, s2);
        } else {
            CP_COMMIT();
        }

        // ks-level software pipeline: load ks+1 frags while issuing ks MMAs
#pragma unroll
        for (int ks = 0; ks < 4; ks++) {
            if (ks < 3) ld_frags(ab, bb, ks + 1, (ks + 1) & 1);
            const int buf = ks & 1;
#pragma unroll
            for (int mt = 0; mt < 4; mt++)
#pragma unroll
                for (int nt = 0; nt < 8; nt++)
                    mma16816(acc[mt][nt], af[buf][mt], bf[buf][nt]);
        }

        if (++stage == 3) stage = 0;
    }

    // ---- epilogue ----
    const int gid = lane >> 2, tig = lane & 3;
#pragma unroll
    for (int mt = 0; mt < 4; mt++) {
        const int r_ = row0 + wm * 64 + mt * 16 + gid;
        const float rs0 = alpha * (rowscale ? rowscale[r_] : 1.0f);
        const float rs1 = alpha * (rowscale ? rowscale[r_ + 8] : 1.0f);
#pragma unroll
        for (int nt = 0; nt < 8; nt++) {
            const int cc = col0 + wn * 64 + nt * 8 + tig * 2;
            const float v0 = rs0 * acc[mt][nt][0];
            const float v1 = rs0 * acc[mt][nt][1];
            const float v2 = rs1 * acc[mt][nt][2];
            const float v3 = rs1 * acc[mt][nt][3];
            if (EPI == 0) {
                *reinterpret_cast<float2*>(&C[(size_t)r_ * ldc + cc]) = make_float2(v0, v1);
                *reinterpret_cast<float2*>(&C[(size_t)(r_ + 8) * ldc + cc]) = make_float2(v2, v3);
            } else if (EPI == 1) {
                h16 p0, p1, q0, q1;
                split2(v0, p0, p1); split2(v1, q0, q1);
                __half2 lo0; lo0.x = p0; lo0.y = q0;
                __half2 lo1; lo1.x = p1; lo1.y = q1;
                *reinterpret_cast<__half2*>(c0 + (size_t)r_ * ldc + cc) = lo0;
                *reinterpret_cast<__half2*>(c1 + (size_t)r_ * ldc + cc) = lo1;
                split2(v2, p0, p1); split2(v3, q0, q1);
                __half2 hi0; hi0.x = p0; hi0.y = q0;
                __half2 hi1; hi1.x = p1; hi1.y = q1;
                *reinterpret_cast<__half2*>(c0 + (size_t)(r_ + 8) * ldc + cc) = hi0;
                *reinterpret_cast<__half2*>(c1 + (size_t)(r_ + 8) * ldc + cc) = hi1;
            } else {
                __half2 lo; lo.x = __float2half_rn(v0); lo.y = __float2half_rn(v1);
                __half2 hi; hi.x = __float2half_rn(v2); hi.y = __float2half_rn(v3);
                *reinterpret_cast<__half2*>(c0 + (size_t)r_ * ldc + cc) = lo;
                *reinterpret_cast<__half2*>(c0 + (size_t)(r_ + 8) * ldc + cc) = hi;
            }
        }
    }
}

template <int EPI, int NSEG>
__global__ __launch_bounds__(256, 1) void gemm_hmma(
    const h16* __restrict__ a0, const h16* __restrict__ a1,
    const h16* __restrict__ b0, const h16* __restrict__ b1,
    float* __restrict__ C, h16* __restrict__ c0, h16* __restrict__ c1,
    const float* __restrict__ rowscale,
    int N, int Kd, int lda, int ldb, int ldc, float alpha)
{
    extern __shared__ char sm[];
    gemm_body<EPI, NSEG>(blockIdx.x, blockIdx.y, sm, a0, a1, b0, b1,
                         C, c0, c1, rowscale, N, Kd, lda, ldb, ldc, alpha);
}

// Merged projections: blocks [0,256) do fused [Q|K] (EPI=1), [256,384) do V^T (EPI=2).
__global__ __launch_bounds__(256, 1) void proj_fused(
    const h16* __restrict__ xp0, const h16* __restrict__ xp1,
    const h16* __restrict__ wqk0, const h16* __restrict__ wqk1,
    h16* __restrict__ qk0, h16* __restrict__ qk1,
    const h16* __restrict__ wv0, const h16* __restrict__ wv1,
    h16* __restrict__ vt)
{
    extern __shared__ char sm[];
    const int id = blockIdx.x;
    if (id < 256) {
        gemm_body<1, 3>(id & 15, id >> 4, sm, xp0, xp1, wqk0, wqk1,
                        nullptr, qk0, qk1, nullptr,
                        2 * DIM, DIM, DIM, DIM, 2 * DIM, 1.0f);
    } else {
        const int j = id - 256;
        gemm_body<2, 3>(j & 31, j >> 5, sm, wv0, wv1, xp0, xp1,
                        nullptr, vt, nullptr, nullptr,
                        SEQ, DIM, DIM, DIM, SEQ, 1.0f);
    }
}

#define GEMM_SMEM 147456

// ---------------------------------------------------------------------------
__global__ __launch_bounds__(256) void split_planes2(
    const float* __restrict__ src, h16* __restrict__ d0, h16* __restrict__ d1, int n)
{
    int i = (blockIdx.x * 256 + threadIdx.x) * 2;
    if (i < n) {
        float2 v = *reinterpret_cast<const float2*>(src + i);
        h16 a0, a1, b0, b1;
        split2(v.x, a0, a1); split2(v.y, b0, b1);
        __half2 p0; p0.x = a0; p0.y = b0;
        __half2 p1; p1.x = a1; p1.y = b1;
        *reinterpret_cast<__half2*>(d0 + i) = p0;
        *reinterpret_cast<__half2*>(d1 + i) = p1;
    }
}

// fp32 [R,C] -> transposed 2 fp16 planes [C,R]; blockIdx.z selects source
__global__ __launch_bounds__(256) void transpose_split3(
    const float* __restrict__ srcA, const float* __restrict__ srcB,
    const float* __restrict__ srcC,
    h16* __restrict__ dA0, h16* __restrict__ dA1,
    h16* __restrict__ dB0, h16* __restrict__ dB1,
    h16* __restrict__ dC0, h16* __restrict__ dC1, int R, int C)
{
    __shared__ float t[32][33];
    const float* src = (blockIdx.z == 0) ? srcA : (blockIdx.z == 1) ? srcB : srcC;
    h16* e0 = (blockIdx.z == 0) ? dA0 : (blockIdx.z == 1) ? dB0 : dC0;
    h16* e1 = (blockIdx.z == 0) ? dA1 : (blockIdx.z == 1) ? dB1 : dC1;
    const int tx = threadIdx.x, ty = threadIdx.y;
    const int r0 = blockIdx.y * 32, c0 = blockIdx.x * 32;
#pragma unroll
    for (int j = 0; j < 32; j += 8)
        t[ty + j][tx] = src[(size_t)(r0 + ty + j) * C + c0 + tx];
    __syncthreads();
#pragma unroll
    for (int j = 0; j < 32; j += 8) {
        float v = t[tx][ty + j];
        h16 h0, h1;
        split2(v, h0, h1);
        size_t o = (size_t)(c0 + ty + j) * R + r0 + tx;
        e0[o] = h0; e1[o] = h1;
    }
}

// ---------------------------------------------------------------------------
// Row softmax (unnormalized): P = exp(s - rowmax) as 2 fp16 planes,
// inv[row] = 1/sum. Normalization folded into PV epilogue.
// ---------------------------------------------------------------------------
__global__ __launch_bounds__(256) void softmax_exp_split2(
    const float* __restrict__ S, h16* __restrict__ P0, h16* __restrict__ P1,
    float* __restrict__ inv)
{
    const int row = blockIdx.x;
    const float* p = S + (size_t)row * SEQ;
    const int tid = threadIdx.x;
    __shared__ float red[256];

    float mx = -INFINITY;
    for (int i = tid; i < SEQ; i += 256) mx = fmaxf(mx, p[i]);
    red[tid] = mx;
    __syncthreads();
#pragma unroll
    for (int s = 128; s > 0; s >>= 1) {
        if (tid < s) red[tid] = fmaxf(red[tid], red[tid + s]);
        __syncthreads();
    }
    mx = red[0];
    __syncthreads();

    const size_t base = (size_t)row * SEQ;
    float sum = 0.0f;
    for (int i = tid * 2; i < SEQ; i += 512) {
        float2 v = *reinterpret_cast<const float2*>(p + i);
        float e0 = expf(v.x - mx);
        float e1 = expf(v.y - mx);
        sum += e0 + e1;
        h16 a0, a1, b0, b1;
        split2(e0, a0, a1); split2(e1, b0, b1);
        __half2 q0; q0.x = a0; q0.y = b0;
        __half2 q1; q1.x = a1; q1.y = b1;
        *reinterpret_cast<__half2*>(P0 + base + i) = q0;
        *reinterpret_cast<__half2*>(P1 + base + i) = q1;
    }
    red[tid] = sum;
    __syncthreads();
#pragma unroll
    for (int s = 128; s > 0; s >>= 1) {
        if (tid < s) red[tid] += red[tid + s];
        __syncthreads();
    }
    if (tid == 0) inv[row] = 1.0f / red[0];
}

// ---------------------------------------------------------------------------
extern "C" void kernel_launch(void* const* d_in, const int* in_sizes, int n_in,
                              void* d_out, int out_size)
{
    const float* x  = (const float*)d_in[0];
    const float* Wq = (const float*)d_in[1];
    const float* Wk = (const float*)d_in[2];
    const float* Wv = (const float*)d_in[3];
    float* out = (float*)d_out;

    h16 *xp, *wqkt, *wvt, *qkp, *vt, *pp;
    float *S, *inv;
    cudaGetSymbolAddress((void**)&xp,   g_xp);
    cudaGetSymbolAddress((void**)&wqkt, g_Wqkt);
    cudaGetSymbolAddress((void**)&wvt,  g_Wvt);
    cudaGetSymbolAddress((void**)&qkp,  g_QKp);
    cudaGetSymbolAddress((void**)&vt,   g_Vt);
    cudaGetSymbolAddress((void**)&S,    g_S);
    cudaGetSymbolAddress((void**)&pp,   g_Pp);
    cudaGetSymbolAddress((void**)&inv,  g_inv);

    const size_t ND = (size_t)SEQ * DIM;      // 4M
    const size_t DD = (size_t)DIM * DIM;      // 1M
    const size_t N2 = (size_t)SEQ * 2 * DIM;  // 8M
    const size_t NN = (size_t)SEQ * SEQ;      // 16M

    h16 *xp0 = xp, *xp1 = xp + ND;
    h16 *wqk0 = wqkt, *wqk1 = wqkt + 2 * DD;
    h16 *wv0 = wvt, *wv1 = wvt + DD;
    h16 *qk0 = qkp, *qk1 = qkp + N2;
    h16 *pp0 = pp, *pp1 = pp + NN;

    cudaFuncSetAttribute((const void*)gemm_hmma<0, 3>, cudaFuncAttributeMaxDynamicSharedMemorySize, GEMM_SMEM);
    cudaFuncSetAttribute((const void*)gemm_hmma<0, 2>, cudaFuncAttributeMaxDynamicSharedMemorySize, GEMM_SMEM);
    cudaFuncSetAttribute((const void*)proj_fused, cudaFuncAttributeMaxDynamicSharedMemorySize, GEMM_SMEM);

    dim3 b256(256);
    dim3 tb(32, 8);

    // 1) split x
    split_planes2<<<(int)(ND / 512), b256>>>(x, xp0, xp1, (int)ND);

    // 2) fused Wq+Wk+Wv transpose (one launch, z=3)
    transpose_split3<<<dim3(DIM / 32, DIM / 32, 3), tb>>>(
        Wq, Wk, Wv, wqk0, wqk1, wqk0 + DD, wqk1 + DD, wv0, wv1, DIM, DIM);

    // 3) merged projections: [Q|K] (EPI=1) + V^T (EPI=2), 384 blocks
    proj_fused<<<384, b256, GEMM_SMEM>>>(
        xp0, xp1, wqk0, wqk1, qk0, qk1, wv0, wv1, vt);

    // 4) scores S = (1/32) Q K^T    (full 3-product accuracy)
    gemm_hmma<0, 3><<<dim3(SEQ / 128, SEQ / 256), b256, GEMM_SMEM>>>(
        qk0, qk1, qk0 + DIM, qk1 + DIM, S, nullptr, nullptr, nullptr,
        SEQ, DIM, 2 * DIM, 2 * DIM, SEQ, 0.03125f);

    // 5) softmax: unnormalized exp planes + 1/sum
    softmax_exp_split2<<<SEQ, b256>>>(S, pp0, pp1, inv);

    // 6) out = diag(inv) * P V   (2 products: p0*v + p1*v; V single plane)
    gemm_hmma<0, 2><<<dim3(DIM / 128, SEQ / 256), b256, GEMM_SMEM>>>(
        pp0, pp1, vt, nullptr, out, nullptr, nullptr, inv,
        DIM, SEQ, SEQ, SEQ, DIM, 1.0f);
}

// round 13
// speedup vs baseline: 3.8120x; 1.0135x over previous
#include <cuda_runtime.h>
#include <cuda_fp16.h>
#include <stdint.h>
#include <math.h>

#define SEQ 4096
#define DIM 1024

typedef __half h16;

// ---------------- static device scratch ----------------
__device__ h16  g_xp[2][SEQ * DIM];                 // x split planes [SEQ, DIM]
__device__ h16  g_Wqkt[2][2 * DIM * DIM];           // [Wq^T ; Wk^T] planes [2048, 1024]
__device__ h16  g_Wvt[2][DIM * DIM];                // Wv^T planes [1024, 1024]
__device__ h16  g_QKp[2][(size_t)SEQ * 2 * DIM];    // [Q | K] planes [SEQ, 2048]
__device__ h16  g_Vt[(size_t)DIM * SEQ];            // V^T single fp16 plane [DIM, SEQ]
__device__ float g_S[(size_t)SEQ * SEQ];
__device__ h16  g_Pp[2][(size_t)SEQ * SEQ];         // exp (unnormalized) planes
__device__ float g_inv[SEQ];                        // per-row 1/sum

// ---------------- helpers ----------------
__device__ __forceinline__ uint32_t smem_u32(const void* p) {
    uint32_t a;
    asm("{ .reg .u64 t; cvta.to.shared.u64 t, %1; cvt.u32.u64 %0, t; }" : "=r"(a) : "l"(p));
    return a;
}
__device__ __forceinline__ uint32_t sw128(uint32_t o) { return o ^ ((o >> 3) & 0x70); }

__device__ __forceinline__ void cp_async16(uint32_t s, const void* g) {
    asm volatile("cp.async.cg.shared.global [%0], [%1], 16;" :: "r"(s), "l"(g));
}
#define CP_COMMIT() asm volatile("cp.async.commit_group;" ::: "memory")
#define CP_WAIT1()  asm volatile("cp.async.wait_group 1;" ::: "memory")

__device__ __forceinline__ void ldsm4(uint32_t& r0, uint32_t& r1, uint32_t& r2, uint32_t& r3, uint32_t a) {
    asm volatile("ldmatrix.sync.aligned.m8n8.x4.shared.b16 {%0,%1,%2,%3}, [%4];"
                 : "=r"(r0), "=r"(r1), "=r"(r2), "=r"(r3) : "r"(a));
}
__device__ __forceinline__ void mma16816(float* c, const uint32_t* a, const uint32_t* b) {
    asm volatile("mma.sync.aligned.m16n8k16.row.col.f32.f16.f16.f32 "
                 "{%0,%1,%2,%3}, {%4,%5,%6,%7}, {%8,%9}, {%0,%1,%2,%3};"
                 : "+f"(c[0]), "+f"(c[1]), "+f"(c[2]), "+f"(c[3])
                 : "r"(a[0]), "r"(a[1]), "r"(a[2]), "r"(a[3]), "r"(b[0]), "r"(b[1]));
}
__device__ __forceinline__ void split2(float v, h16& x0, h16& x1) {
    x0 = __float2half_rn(v);
    x1 = __float2half_rn(v - __half2float(x0));
}

// ---------------------------------------------------------------------------
// GEMM body:  C[M,N] = alpha * rowscale[m] * A[M,K] * B[N,K]^T  (K-major planes)
// NSEG=3: a0b0 + a0b1 + a1b0.  NSEG=2: a0b0 + a1b0 (B single plane).
// CTA tile 128x128, BK=64, 8 warps (2x4 of 64x32), 3-stage cp.async pipeline
// (3 x 32KB smem -> 2 CTAs/SM, 16 warps/SM for latency hiding).
// EPI=0: fp32 C. EPI=1: 2 fp16 split planes. EPI=2: single fp16 plane.
// ---------------------------------------------------------------------------
template <int EPI, int NSEG>
__device__ __forceinline__ void gemm_body(
    int bx, int by, char* sm,
    const h16* __restrict__ a0, const h16* __restrict__ a1,
    const h16* __restrict__ b0, const h16* __restrict__ b1,
    float* __restrict__ C, h16* __restrict__ c0, h16* __restrict__ c1,
    const float* __restrict__ rowscale,
    int N, int Kd, int lda, int ldb, int ldc, float alpha)
{
    const uint32_t smu = smem_u32(sm);
    const int tid = threadIdx.x;
    const int wid = tid >> 5, lane = tid & 31;
    const int wm = wid >> 2, wn = wid & 3;            // 2x4 warp grid, 64x32 tiles
    const int row0 = by * 128, col0 = bx * 128;

    const h16* segA[3];
    const h16* segB[3];
    if (NSEG == 3) {
        segA[0] = a0; segA[1] = a0; segA[2] = a1;
        segB[0] = b0; segB[1] = b1; segB[2] = b0;
    } else {
        segA[0] = a0; segA[1] = a1; segA[2] = a1;
        segB[0] = b0; segB[1] = b0; segB[2] = b0;
    }
    const int cpk = Kd >> 6;
    const int nc = NSEG * cpk;

    const int gr = tid >> 3;       // 0..31 base row
    const int gc = tid & 7;        // 16B granule in 128B row

    float acc[4][4][4];
#pragma unroll
    for (int i = 0; i < 4; i++)
#pragma unroll
        for (int j = 0; j < 4; j++)
#pragma unroll
            for (int q = 0; q < 4; q++) acc[i][j][q] = 0.0f;

    // fragment smem base offsets (lane-dependent only)
    const int arr = wm * 64 + (lane & 15);
    const uint32_t abase_lane = (uint32_t)(arr * 128 + ((lane >> 4) << 4));
    const int bnn = wn * 32 + ((lane >> 4) << 3) + (lane & 7);
    const uint32_t bbase_lane = (uint32_t)(bnn * 128 + (((lane >> 3) & 1) << 4));

    auto load_chunk = [&](int c, int b) {
        const int seg = c / cpk;
        const int kc = (c - seg * cpk) << 6;
        const h16* Ag = segA[seg];
        const h16* Bg = segB[seg];
        const uint32_t ab = smu + (uint32_t)b * 32768u;     // 32KB stage
        const uint32_t bb = ab + 16384u;                    // A:16KB, B:16KB
#pragma unroll
        for (int q = 0; q < 4; q++) {                       // A: 128 rows
            const int r = gr + q * 32;
            const uint32_t off = sw128((uint32_t)(r * 128 + gc * 16));
            cp_async16(ab + off, Ag + (size_t)(row0 + r) * lda + kc + gc * 8);
        }
#pragma unroll
        for (int q = 0; q < 4; q++) {                       // B: 128 rows
            const int r = gr + q * 32;
            const uint32_t off = sw128((uint32_t)(r * 128 + gc * 16));
            cp_async16(bb + off, Bg + (size_t)(col0 + r) * ldb + kc + gc * 8);
        }
        CP_COMMIT();
    };

    load_chunk(0, 0);
    load_chunk(1, 1);

    int stage = 0;
    for (int c = 0; c < nc; c++) {
        CP_WAIT1();            // chunk c resident
        __syncthreads();       // chunk c-1 consumers done -> its stage is free

        const uint32_t ab = smu + (uint32_t)stage * 32768u;
        const uint32_t bb = ab + 16384u;

        // issue next chunk's cp.async (into the stage freed by iter c-1)
        if (c + 2 < nc) {
            int s2 = stage + 2; if (s2 >= 3) s2 -= 3;
            load_chunk(c + 2, s2);
        } else {
            CP_COMMIT();
        }

#pragma unroll
        for (int ks = 0; ks < 4; ks++) {
            uint32_t af[4][4];
            uint32_t bf[4][2];
#pragma unroll
            for (int mt = 0; mt < 4; mt++) {
                const uint32_t off = sw128(abase_lane + (uint32_t)(mt * 16 * 128 + ks * 32));
                ldsm4(af[mt][0], af[mt][1], af[mt][2], af[mt][3], ab + off);
            }
#pragma unroll
            for (int nt2 = 0; nt2 < 2; nt2++) {
                const uint32_t off = sw128(bbase_lane + (uint32_t)(nt2 * 16 * 128 + ks * 32));
                uint32_t r0, r1, r2, r3;
                ldsm4(r0, r1, r2, r3, bb + off);
                bf[nt2 * 2][0] = r0;     bf[nt2 * 2][1] = r1;
                bf[nt2 * 2 + 1][0] = r2; bf[nt2 * 2 + 1][1] = r3;
            }
#pragma unroll
            for (int mt = 0; mt < 4; mt++)
#pragma unroll
                for (int nt = 0; nt < 4; nt++)
                    mma16816(acc[mt][nt], af[mt], bf[nt]);
        }

        if (++stage == 3) stage = 0;
    }

    // ---- epilogue ----
    const int gid = lane >> 2, tig = lane & 3;
#pragma unroll
    for (int mt = 0; mt < 4; mt++) {
        const int r_ = row0 + wm * 64 + mt * 16 + gid;
        const float rs0 = alpha * (rowscale ? rowscale[r_] : 1.0f);
        const float rs1 = alpha * (rowscale ? rowscale[r_ + 8] : 1.0f);
#pragma unroll
        for (int nt = 0; nt < 4; nt++) {
            const int cc = col0 + wn * 32 + nt * 8 + tig * 2;
            const float v0 = rs0 * acc[mt][nt][0];
            const float v1 = rs0 * acc[mt][nt][1];
            const float v2 = rs1 * acc[mt][nt][2];
            const float v3 = rs1 * acc[mt][nt][3];
            if (EPI == 0) {
                *reinterpret_cast<float2*>(&C[(size_t)r_ * ldc + cc]) = make_float2(v0, v1);
                *reinterpret_cast<float2*>(&C[(size_t)(r_ + 8) * ldc + cc]) = make_float2(v2, v3);
            } else if (EPI == 1) {
                h16 p0, p1, q0, q1;
                split2(v0, p0, p1); split2(v1, q0, q1);
                __half2 lo0; lo0.x = p0; lo0.y = q0;
                __half2 lo1; lo1.x = p1; lo1.y = q1;
                *reinterpret_cast<__half2*>(c0 + (size_t)r_ * ldc + cc) = lo0;
                *reinterpret_cast<__half2*>(c1 + (size_t)r_ * ldc + cc) = lo1;
                split2(v2, p0, p1); split2(v3, q0, q1);
                __half2 hi0; hi0.x = p0; hi0.y = q0;
                __half2 hi1; hi1.x = p1; hi1.y = q1;
                *reinterpret_cast<__half2*>(c0 + (size_t)(r_ + 8) * ldc + cc) = hi0;
                *reinterpret_cast<__half2*>(c1 + (size_t)(r_ + 8) * ldc + cc) = hi1;
            } else {
                __half2 lo; lo.x = __float2half_rn(v0); lo.y = __float2half_rn(v1);
                __half2 hi; hi.x = __float2half_rn(v2); hi.y = __float2half_rn(v3);
                *reinterpret_cast<__half2*>(c0 + (size_t)r_ * ldc + cc) = lo;
                *reinterpret_cast<__half2*>(c0 + (size_t)(r_ + 8) * ldc + cc) = hi;
            }
        }
    }
}

template <int EPI, int NSEG>
__global__ __launch_bounds__(256, 2) void gemm_hmma(
    const h16* __restrict__ a0, const h16* __restrict__ a1,
    const h16* __restrict__ b0, const h16* __restrict__ b1,
    float* __restrict__ C, h16* __restrict__ c0, h16* __restrict__ c1,
    const float* __restrict__ rowscale,
    int N, int Kd, int lda, int ldb, int ldc, float alpha)
{
    extern __shared__ char sm[];
    gemm_body<EPI, NSEG>(blockIdx.x, blockIdx.y, sm, a0, a1, b0, b1,
                         C, c0, c1, rowscale, N, Kd, lda, ldb, ldc, alpha);
}

// Merged projections: blocks [0,512) do fused [Q|K] (EPI=1), [512,768) do V^T (EPI=2).
__global__ __launch_bounds__(256, 2) void proj_fused(
    const h16* __restrict__ xp0, const h16* __restrict__ xp1,
    const h16* __restrict__ wqk0, const h16* __restrict__ wqk1,
    h16* __restrict__ qk0, h16* __restrict__ qk1,
    const h16* __restrict__ wv0, const h16* __restrict__ wv1,
    h16* __restrict__ vt)
{
    extern __shared__ char sm[];
    const int id = blockIdx.x;
    if (id < 512) {
        gemm_body<1, 3>(id & 15, id >> 4, sm, xp0, xp1, wqk0, wqk1,
                        nullptr, qk0, qk1, nullptr,
                        2 * DIM, DIM, DIM, DIM, 2 * DIM, 1.0f);
    } else {
        const int j = id - 512;
        gemm_body<2, 3>(j & 31, j >> 5, sm, wv0, wv1, xp0, xp1,
                        nullptr, vt, nullptr, nullptr,
                        SEQ, DIM, DIM, DIM, SEQ, 1.0f);
    }
}

#define GEMM_SMEM 98304

// ---------------------------------------------------------------------------
__global__ __launch_bounds__(256) void split_planes2(
    const float* __restrict__ src, h16* __restrict__ d0, h16* __restrict__ d1, int n)
{
    int i = (blockIdx.x * 256 + threadIdx.x) * 2;
    if (i < n) {
        float2 v = *reinterpret_cast<const float2*>(src + i);
        h16 a0, a1, b0, b1;
        split2(v.x, a0, a1); split2(v.y, b0, b1);
        __half2 p0; p0.x = a0; p0.y = b0;
        __half2 p1; p1.x = a1; p1.y = b1;
        *reinterpret_cast<__half2*>(d0 + i) = p0;
        *reinterpret_cast<__half2*>(d1 + i) = p1;
    }
}

// fp32 [R,C] -> transposed 2 fp16 planes [C,R]; blockIdx.z selects source
__global__ __launch_bounds__(256) void transpose_split3(
    const float* __restrict__ srcA, const float* __restrict__ srcB,
    const float* __restrict__ srcC,
    h16* __restrict__ dA0, h16* __restrict__ dA1,
    h16* __restrict__ dB0, h16* __restrict__ dB1,
    h16* __restrict__ dC0, h16* __restrict__ dC1, int R, int C)
{
    __shared__ float t[32][33];
    const float* src = (blockIdx.z == 0) ? srcA : (blockIdx.z == 1) ? srcB : srcC;
    h16* e0 = (blockIdx.z == 0) ? dA0 : (blockIdx.z == 1) ? dB0 : dC0;
    h16* e1 = (blockIdx.z == 0) ? dA1 : (blockIdx.z == 1) ? dB1 : dC1;
    const int tx = threadIdx.x, ty = threadIdx.y;
    const int r0 = blockIdx.y * 32, c0 = blockIdx.x * 32;
#pragma unroll
    for (int j = 0; j < 32; j += 8)
        t[ty + j][tx] = src[(size_t)(r0 + ty + j) * C + c0 + tx];
    __syncthreads();
#pragma unroll
    for (int j = 0; j < 32; j += 8) {
        float v = t[tx][ty + j];
        h16 h0, h1;
        split2(v, h0, h1);
        size_t o = (size_t)(c0 + ty + j) * R + r0 + tx;
        e0[o] = h0; e1[o] = h1;
    }
}

// ---------------------------------------------------------------------------
// Row softmax (unnormalized): P = exp(s - rowmax) as 2 fp16 planes,
// inv[row] = 1/sum. Normalization folded into PV epilogue.
// ---------------------------------------------------------------------------
__global__ __launch_bounds__(256) void softmax_exp_split2(
    const float* __restrict__ S, h16* __restrict__ P0, h16* __restrict__ P1,
    float* __restrict__ inv)
{
    const int row = blockIdx.x;
    const float* p = S + (size_t)row * SEQ;
    const int tid = threadIdx.x;
    __shared__ float red[256];

    float mx = -INFINITY;
    for (int i = tid; i < SEQ; i += 256) mx = fmaxf(mx, p[i]);
    red[tid] = mx;
    __syncthreads();
#pragma unroll
    for (int s = 128; s > 0; s >>= 1) {
        if (tid < s) red[tid] = fmaxf(red[tid], red[tid + s]);
        __syncthreads();
    }
    mx = red[0];
    __syncthreads();

    const size_t base = (size_t)row * SEQ;
    float sum = 0.0f;
    for (int i = tid * 2; i < SEQ; i += 512) {
        float2 v = *reinterpret_cast<const float2*>(p + i);
        float e0 = expf(v.x - mx);
        float e1 = expf(v.y - mx);
        sum += e0 + e1;
        h16 a0, a1, b0, b1;
        split2(e0, a0, a1); split2(e1, b0, b1);
        __half2 q0; q0.x = a0; q0.y = b0;
        __half2 q1; q1.x = a1; q1.y = b1;
        *reinterpret_cast<__half2*>(P0 + base + i) = q0;
        *reinterpret_cast<__half2*>(P1 + base + i) = q1;
    }
    red[tid] = sum;
    __syncthreads();
#pragma unroll
    for (int s = 128; s > 0; s >>= 1) {
        if (tid < s) red[tid] += red[tid + s];
        __syncthreads();
    }
    if (tid == 0) inv[row] = 1.0f / red[0];
}

// ---------------------------------------------------------------------------
extern "C" void kernel_launch(void* const* d_in, const int* in_sizes, int n_in,
                              void* d_out, int out_size)
{
    const float* x  = (const float*)d_in[0];
    const float* Wq = (const float*)d_in[1];
    const float* Wk = (const float*)d_in[2];
    const float* Wv = (const float*)d_in[3];
    float* out = (float*)d_out;

    h16 *xp, *wqkt, *wvt, *qkp, *vt, *pp;
    float *S, *inv;
    cudaGetSymbolAddress((void**)&xp,   g_xp);
    cudaGetSymbolAddress((void**)&wqkt, g_Wqkt);
    cudaGetSymbolAddress((void**)&wvt,  g_Wvt);
    cudaGetSymbolAddress((void**)&qkp,  g_QKp);
    cudaGetSymbolAddress((void**)&vt,   g_Vt);
    cudaGetSymbolAddress((void**)&S,    g_S);
    cudaGetSymbolAddress((void**)&pp,   g_Pp);
    cudaGetSymbolAddress((void**)&inv,  g_inv);

    const size_t ND = (size_t)SEQ * DIM;      // 4M
    const size_t DD = (size_t)DIM * DIM;      // 1M
    const size_t N2 = (size_t)SEQ * 2 * DIM;  // 8M
    const size_t NN = (size_t)SEQ * SEQ;      // 16M

    h16 *xp0 = xp, *xp1 = xp + ND;
    h16 *wqk0 = wqkt, *wqk1 = wqkt + 2 * DD;
    h16 *wv0 = wvt, *wv1 = wvt + DD;
    h16 *qk0 = qkp, *qk1 = qkp + N2;
    h16 *pp0 = pp, *pp1 = pp + NN;

    cudaFuncSetAttribute((const void*)gemm_hmma<0, 3>, cudaFuncAttributeMaxDynamicSharedMemorySize, GEMM_SMEM);
    cudaFuncSetAttribute((const void*)gemm_hmma<0, 2>, cudaFuncAttributeMaxDynamicSharedMemorySize, GEMM_SMEM);
    cudaFuncSetAttribute((const void*)proj_fused, cudaFuncAttributeMaxDynamicSharedMemorySize, GEMM_SMEM);

    dim3 b256(256);
    dim3 tb(32, 8);

    // 1) split x
    split_planes2<<<(int)(ND / 512), b256>>>(x, xp0, xp1, (int)ND);

    // 2) fused Wq+Wk+Wv transpose (one launch, z=3)
    transpose_split3<<<dim3(DIM / 32, DIM / 32, 3), tb>>>(
        Wq, Wk, Wv, wqk0, wqk1, wqk0 + DD, wqk1 + DD, wv0, wv1, DIM, DIM);

    // 3) merged projections: [Q|K] (EPI=1) + V^T (EPI=2), 768 blocks
    proj_fused<<<768, b256, GEMM_SMEM>>>(
        xp0, xp1, wqk0, wqk1, qk0, qk1, wv0, wv1, vt);

    // 4) scores S = (1/32) Q K^T    (full 3-product accuracy)
    gemm_hmma<0, 3><<<dim3(SEQ / 128, SEQ / 128), b256, GEMM_SMEM>>>(
        qk0, qk1, qk0 + DIM, qk1 + DIM, S, nullptr, nullptr, nullptr,
        SEQ, DIM, 2 * DIM, 2 * DIM, SEQ, 0.03125f);

    // 5) softmax: unnormalized exp planes + 1/sum
    softmax_exp_split2<<<SEQ, b256>>>(S, pp0, pp1, inv);

    // 6) out = diag(inv) * P V   (2 products: p0*v + p1*v; V single plane)
    gemm_hmma<0, 2><<<dim3(DIM / 128, SEQ / 128), b256, GEMM_SMEM>>>(
        pp0, pp1, vt, nullptr, out, nullptr, nullptr, inv,
        DIM, SEQ, SEQ, SEQ, DIM, 1.0f);
}

// round 14
// speedup vs baseline: 4.5086x; 1.1827x over previous
#include <cuda_runtime.h>
#include <cuda_fp16.h>
#include <stdint.h>
#include <math.h>

#define SEQ 4096
#define DIM 1024

typedef __half h16;

// ---------------- static device scratch ----------------
__device__ h16  g_xp[2][SEQ * DIM];                 // x split planes [SEQ, DIM]
__device__ h16  g_Wqkt[2][2 * DIM * DIM];           // [Wq^T ; Wk^T] planes [2048, 1024]
__device__ h16  g_Wvt[2][DIM * DIM];                // Wv^T planes [1024, 1024]
__device__ h16  g_QKp[2][(size_t)SEQ * 2 * DIM];    // [Q | K] planes [SEQ, 2048]
__device__ h16  g_Vt[(size_t)DIM * SEQ];            // V^T single fp16 plane [DIM, SEQ]
__device__ float g_S[(size_t)SEQ * SEQ];
__device__ h16  g_Pp[(size_t)SEQ * SEQ];            // exp (unnormalized) single plane
__device__ float g_inv[SEQ];                        // per-row 1/sum

// ---------------- helpers ----------------
__device__ __forceinline__ uint32_t smem_u32(const void* p) {
    uint32_t a;
    asm("{ .reg .u64 t; cvta.to.shared.u64 t, %1; cvt.u32.u64 %0, t; }" : "=r"(a) : "l"(p));
    return a;
}
__device__ __forceinline__ uint32_t sw128(uint32_t o) { return o ^ ((o >> 3) & 0x70); }

__device__ __forceinline__ void cp_async16(uint32_t s, const void* g) {
    asm volatile("cp.async.cg.shared.global [%0], [%1], 16;" :: "r"(s), "l"(g));
}
#define CP_COMMIT() asm volatile("cp.async.commit_group;" ::: "memory")
#define CP_WAIT1()  asm volatile("cp.async.wait_group 1;" ::: "memory")

__device__ __forceinline__ void ldsm4(uint32_t& r0, uint32_t& r1, uint32_t& r2, uint32_t& r3, uint32_t a) {
    asm volatile("ldmatrix.sync.aligned.m8n8.x4.shared.b16 {%0,%1,%2,%3}, [%4];"
                 : "=r"(r0), "=r"(r1), "=r"(r2), "=r"(r3) : "r"(a));
}
__device__ __forceinline__ void mma16816(float* c, const uint32_t* a, const uint32_t* b) {
    asm volatile("mma.sync.aligned.m16n8k16.row.col.f32.f16.f16.f32 "
                 "{%0,%1,%2,%3}, {%4,%5,%6,%7}, {%8,%9}, {%0,%1,%2,%3};"
                 : "+f"(c[0]), "+f"(c[1]), "+f"(c[2]), "+f"(c[3])
                 : "r"(a[0]), "r"(a[1]), "r"(a[2]), "r"(a[3]), "r"(b[0]), "r"(b[1]));
}
__device__ __forceinline__ void split2(float v, h16& x0, h16& x1) {
    x0 = __float2half_rn(v);
    x1 = __float2half_rn(v - __half2float(x0));
}

// ---------------------------------------------------------------------------
// GEMM body:  C[M,N] = alpha * rowscale[m] * A[M,K] * B[N,K]^T  (K-major planes)
// NSEG=3: a0b0 + a0b1 + a1b0.  NSEG=2: a0b0 + a1b0.  NSEG=1: a0b0 only.
// CTA tile 128x128, BK=64, 8 warps (2x4 of 64x32), 3-stage cp.async pipeline
// (3 x 32KB smem -> 2 CTAs/SM, 16 warps/SM for latency hiding).
// EPI=0: fp32 C. EPI=1: 2 fp16 split planes. EPI=2: single fp16 plane.
// ---------------------------------------------------------------------------
template <int EPI, int NSEG>
__device__ __forceinline__ void gemm_body(
    int bx, int by, char* sm,
    const h16* __restrict__ a0, const h16* __restrict__ a1,
    const h16* __restrict__ b0, const h16* __restrict__ b1,
    float* __restrict__ C, h16* __restrict__ c0, h16* __restrict__ c1,
    const float* __restrict__ rowscale,
    int N, int Kd, int lda, int ldb, int ldc, float alpha)
{
    const uint32_t smu = smem_u32(sm);
    const int tid = threadIdx.x;
    const int wid = tid >> 5, lane = tid & 31;
    const int wm = wid >> 2, wn = wid & 3;            // 2x4 warp grid, 64x32 tiles
    const int row0 = by * 128, col0 = bx * 128;

    const h16* segA[3];
    const h16* segB[3];
    if (NSEG == 3) {
        segA[0] = a0; segA[1] = a0; segA[2] = a1;
        segB[0] = b0; segB[1] = b1; segB[2] = b0;
    } else if (NSEG == 2) {
        segA[0] = a0; segA[1] = a1; segA[2] = a1;
        segB[0] = b0; segB[1] = b0; segB[2] = b0;
    } else {
        segA[0] = a0; segA[1] = a0; segA[2] = a0;
        segB[0] = b0; segB[1] = b0; segB[2] = b0;
    }
    const int cpk = Kd >> 6;
    const int nc = NSEG * cpk;

    const int gr = tid >> 3;       // 0..31 base row
    const int gc = tid & 7;        // 16B granule in 128B row

    float acc[4][4][4];
#pragma unroll
    for (int i = 0; i < 4; i++)
#pragma unroll
        for (int j = 0; j < 4; j++)
#pragma unroll
            for (int q = 0; q < 4; q++) acc[i][j][q] = 0.0f;

    // fragment smem base offsets (lane-dependent only)
    const int arr = wm * 64 + (lane & 15);
    const uint32_t abase_lane = (uint32_t)(arr * 128 + ((lane >> 4) << 4));
    const int bnn = wn * 32 + ((lane >> 4) << 3) + (lane & 7);
    const uint32_t bbase_lane = (uint32_t)(bnn * 128 + (((lane >> 3) & 1) << 4));

    auto load_chunk = [&](int c, int b) {
        const int seg = c / cpk;
        const int kc = (c - seg * cpk) << 6;
        const h16* Ag = segA[seg];
        const h16* Bg = segB[seg];
        const uint32_t ab = smu + (uint32_t)b * 32768u;     // 32KB stage
        const uint32_t bb = ab + 16384u;                    // A:16KB, B:16KB
#pragma unroll
        for (int q = 0; q < 4; q++) {                       // A: 128 rows
            const int r = gr + q * 32;
            const uint32_t off = sw128((uint32_t)(r * 128 + gc * 16));
            cp_async16(ab + off, Ag + (size_t)(row0 + r) * lda + kc + gc * 8);
        }
#pragma unroll
        for (int q = 0; q < 4; q++) {                       // B: 128 rows
            const int r = gr + q * 32;
            const uint32_t off = sw128((uint32_t)(r * 128 + gc * 16));
            cp_async16(bb + off, Bg + (size_t)(col0 + r) * ldb + kc + gc * 8);
        }
        CP_COMMIT();
    };

    load_chunk(0, 0);
    load_chunk(1, 1);

    int stage = 0;
    for (int c = 0; c < nc; c++) {
        CP_WAIT1();            // chunk c resident
        __syncthreads();       // chunk c-1 consumers done -> its stage is free

        const uint32_t ab = smu + (uint32_t)stage * 32768u;
        const uint32_t bb = ab + 16384u;

        // issue next chunk's cp.async (into the stage freed by iter c-1)
        if (c + 2 < nc) {
            int s2 = stage + 2; if (s2 >= 3) s2 -= 3;
            load_chunk(c + 2, s2);
        } else {
            CP_COMMIT();
        }

#pragma unroll
        for (int ks = 0; ks < 4; ks++) {
            uint32_t af[4][4];
            uint32_t bf[4][2];
#pragma unroll
            for (int mt = 0; mt < 4; mt++) {
                const uint32_t off = sw128(abase_lane + (uint32_t)(mt * 16 * 128 + ks * 32));
                ldsm4(af[mt][0], af[mt][1], af[mt][2], af[mt][3], ab + off);
            }
#pragma unroll
            for (int nt2 = 0; nt2 < 2; nt2++) {
                const uint32_t off = sw128(bbase_lane + (uint32_t)(nt2 * 16 * 128 + ks * 32));
                uint32_t r0, r1, r2, r3;
                ldsm4(r0, r1, r2, r3, bb + off);
                bf[nt2 * 2][0] = r0;     bf[nt2 * 2][1] = r1;
                bf[nt2 * 2 + 1][0] = r2; bf[nt2 * 2 + 1][1] = r3;
            }
#pragma unroll
            for (int mt = 0; mt < 4; mt++)
#pragma unroll
                for (int nt = 0; nt < 4; nt++)
                    mma16816(acc[mt][nt], af[mt], bf[nt]);
        }

        if (++stage == 3) stage = 0;
    }

    // ---- epilogue ----
    const int gid = lane >> 2, tig = lane & 3;
#pragma unroll
    for (int mt = 0; mt < 4; mt++) {
        const int r_ = row0 + wm * 64 + mt * 16 + gid;
        const float rs0 = alpha * (rowscale ? rowscale[r_] : 1.0f);
        const float rs1 = alpha * (rowscale ? rowscale[r_ + 8] : 1.0f);
#pragma unroll
        for (int nt = 0; nt < 4; nt++) {
            const int cc = col0 + wn * 32 + nt * 8 + tig * 2;
            const float v0 = rs0 * acc[mt][nt][0];
            const float v1 = rs0 * acc[mt][nt][1];
            const float v2 = rs1 * acc[mt][nt][2];
            const float v3 = rs1 * acc[mt][nt][3];
            if (EPI == 0) {
                *reinterpret_cast<float2*>(&C[(size_t)r_ * ldc + cc]) = make_float2(v0, v1);
                *reinterpret_cast<float2*>(&C[(size_t)(r_ + 8) * ldc + cc]) = make_float2(v2, v3);
            } else if (EPI == 1) {
                h16 p0, p1, q0, q1;
                split2(v0, p0, p1); split2(v1, q0, q1);
                __half2 lo0; lo0.x = p0; lo0.y = q0;
                __half2 lo1; lo1.x = p1; lo1.y = q1;
                *reinterpret_cast<__half2*>(c0 + (size_t)r_ * ldc + cc) = lo0;
                *reinterpret_cast<__half2*>(c1 + (size_t)r_ * ldc + cc) = lo1;
                split2(v2, p0, p1); split2(v3, q0, q1);
                __half2 hi0; hi0.x = p0; hi0.y = q0;
                __half2 hi1; hi1.x = p1; hi1.y = q1;
                *reinterpret_cast<__half2*>(c0 + (size_t)(r_ + 8) * ldc + cc) = hi0;
                *reinterpret_cast<__half2*>(c1 + (size_t)(r_ + 8) * ldc + cc) = hi1;
            } else {
                __half2 lo; lo.x = __float2half_rn(v0); lo.y = __float2half_rn(v1);
                __half2 hi; hi.x = __float2half_rn(v2); hi.y = __float2half_rn(v3);
                *reinterpret_cast<__half2*>(c0 + (size_t)r_ * ldc + cc) = lo;
                *reinterpret_cast<__half2*>(c0 + (size_t)(r_ + 8) * ldc + cc) = hi;
            }
        }
    }
}

template <int EPI, int NSEG>
__global__ __launch_bounds__(256, 2) void gemm_hmma(
    const h16* __restrict__ a0, const h16* __restrict__ a1,
    const h16* __restrict__ b0, const h16* __restrict__ b1,
    float* __restrict__ C, h16* __restrict__ c0, h16* __restrict__ c1,
    const float* __restrict__ rowscale,
    int N, int Kd, int lda, int ldb, int ldc, float alpha)
{
    extern __shared__ char sm[];
    gemm_body<EPI, NSEG>(blockIdx.x, blockIdx.y, sm, a0, a1, b0, b1,
                         C, c0, c1, rowscale, N, Kd, lda, ldb, ldc, alpha);
}

// Merged projections: blocks [0,512) do fused [Q|K] (EPI=1), [512,768) do V^T (EPI=2).
__global__ __launch_bounds__(256, 2) void proj_fused(
    const h16* __restrict__ xp0, const h16* __restrict__ xp1,
    const h16* __restrict__ wqk0, const h16* __restrict__ wqk1,
    h16* __restrict__ qk0, h16* __restrict__ qk1,
    const h16* __restrict__ wv0, const h16* __restrict__ wv1,
    h16* __restrict__ vt)
{
    extern __shared__ char sm[];
    const int id = blockIdx.x;
    if (id < 512) {
        gemm_body<1, 3>(id & 15, id >> 4, sm, xp0, xp1, wqk0, wqk1,
                        nullptr, qk0, qk1, nullptr,
                        2 * DIM, DIM, DIM, DIM, 2 * DIM, 1.0f);
    } else {
        const int j = id - 512;
        gemm_body<2, 3>(j & 31, j >> 5, sm, wv0, wv1, xp0, xp1,
                        nullptr, vt, nullptr, nullptr,
                        SEQ, DIM, DIM, DIM, SEQ, 1.0f);
    }
}

#define GEMM_SMEM 98304

// ---------------------------------------------------------------------------
__global__ __launch_bounds__(256) void split_planes2(
    const float* __restrict__ src, h16* __restrict__ d0, h16* __restrict__ d1, int n)
{
    int i = (blockIdx.x * 256 + threadIdx.x) * 2;
    if (i < n) {
        float2 v = *reinterpret_cast<const float2*>(src + i);
        h16 a0, a1, b0, b1;
        split2(v.x, a0, a1); split2(v.y, b0, b1);
        __half2 p0; p0.x = a0; p0.y = b0;
        __half2 p1; p1.x = a1; p1.y = b1;
        *reinterpret_cast<__half2*>(d0 + i) = p0;
        *reinterpret_cast<__half2*>(d1 + i) = p1;
    }
}

// fp32 [R,C] -> transposed 2 fp16 planes [C,R]; blockIdx.z selects source
__global__ __launch_bounds__(256) void transpose_split3(
    const float* __restrict__ srcA, const float* __restrict__ srcB,
    const float* __restrict__ srcC,
    h16* __restrict__ dA0, h16* __restrict__ dA1,
    h16* __restrict__ dB0, h16* __restrict__ dB1,
    h16* __restrict__ dC0, h16* __restrict__ dC1, int R, int C)
{
    __shared__ float t[32][33];
    const float* src = (blockIdx.z == 0) ? srcA : (blockIdx.z == 1) ? srcB : srcC;
    h16* e0 = (blockIdx.z == 0) ? dA0 : (blockIdx.z == 1) ? dB0 : dC0;
    h16* e1 = (blockIdx.z == 0) ? dA1 : (blockIdx.z == 1) ? dB1 : dC1;
    const int tx = threadIdx.x, ty = threadIdx.y;
    const int r0 = blockIdx.y * 32, c0 = blockIdx.x * 32;
#pragma unroll
    for (int j = 0; j < 32; j += 8)
        t[ty + j][tx] = src[(size_t)(r0 + ty + j) * C + c0 + tx];
    __syncthreads();
#pragma unroll
    for (int j = 0; j < 32; j += 8) {
        float v = t[tx][ty + j];
        h16 h0, h1;
        split2(v, h0, h1);
        size_t o = (size_t)(c0 + ty + j) * R + r0 + tx;
        e0[o] = h0; e1[o] = h1;
    }
}

// ---------------------------------------------------------------------------
// Row softmax (unnormalized): P = exp(s - rowmax) as ONE fp16 plane,
// inv[row] = 1/sum. Normalization folded into PV epilogue.
// ---------------------------------------------------------------------------
__global__ __launch_bounds__(256) void softmax_exp1(
    const float* __restrict__ S, h16* __restrict__ P0, float* __restrict__ inv)
{
    const int row = blockIdx.x;
    const float* p = S + (size_t)row * SEQ;
    const int tid = threadIdx.x;
    __shared__ float red[256];

    float mx = -INFINITY;
    for (int i = tid; i < SEQ; i += 256) mx = fmaxf(mx, p[i]);
    red[tid] = mx;
    __syncthreads();
#pragma unroll
    for (int s = 128; s > 0; s >>= 1) {
        if (tid < s) red[tid] = fmaxf(red[tid], red[tid + s]);
        __syncthreads();
    }
    mx = red[0];
    __syncthreads();

    const size_t base = (size_t)row * SEQ;
    float sum = 0.0f;
    for (int i = tid * 2; i < SEQ; i += 512) {
        float2 v = *reinterpret_cast<const float2*>(p + i);
        float e0 = expf(v.x - mx);
        float e1 = expf(v.y - mx);
        sum += e0 + e1;
        __half2 q0; q0.x = __float2half_rn(e0); q0.y = __float2half_rn(e1);
        *reinterpret_cast<__half2*>(P0 + base + i) = q0;
    }
    red[tid] = sum;
    __syncthreads();
#pragma unroll
    for (int s = 128; s > 0; s >>= 1) {
        if (tid < s) red[tid] += red[tid + s];
        __syncthreads();
    }
    if (tid == 0) inv[row] = 1.0f / red[0];
}

// ---------------------------------------------------------------------------
extern "C" void kernel_launch(void* const* d_in, const int* in_sizes, int n_in,
                              void* d_out, int out_size)
{
    const float* x  = (const float*)d_in[0];
    const float* Wq = (const float*)d_in[1];
    const float* Wk = (const float*)d_in[2];
    const float* Wv = (const float*)d_in[3];
    float* out = (float*)d_out;

    h16 *xp, *wqkt, *wvt, *qkp, *vt, *pp;
    float *S, *inv;
    cudaGetSymbolAddress((void**)&xp,   g_xp);
    cudaGetSymbolAddress((void**)&wqkt, g_Wqkt);
    cudaGetSymbolAddress((void**)&wvt,  g_Wvt);
    cudaGetSymbolAddress((void**)&qkp,  g_QKp);
    cudaGetSymbolAddress((void**)&vt,   g_Vt);
    cudaGetSymbolAddress((void**)&S,    g_S);
    cudaGetSymbolAddress((void**)&pp,   g_Pp);
    cudaGetSymbolAddress((void**)&inv,  g_inv);

    const size_t ND = (size_t)SEQ * DIM;      // 4M
    const size_t DD = (size_t)DIM * DIM;      // 1M
    const size_t N2 = (size_t)SEQ * 2 * DIM;  // 8M

    h16 *xp0 = xp, *xp1 = xp + ND;
    h16 *wqk0 = wqkt, *wqk1 = wqkt + 2 * DD;
    h16 *wv0 = wvt, *wv1 = wvt + DD;
    h16 *qk0 = qkp, *qk1 = qkp + N2;

    cudaFuncSetAttribute((const void*)gemm_hmma<0, 3>, cudaFuncAttributeMaxDynamicSharedMemorySize, GEMM_SMEM);
    cudaFuncSetAttribute((const void*)gemm_hmma<0, 1>, cudaFuncAttributeMaxDynamicSharedMemorySize, GEMM_SMEM);
    cudaFuncSetAttribute((const void*)proj_fused, cudaFuncAttributeMaxDynamicSharedMemorySize, GEMM_SMEM);

    dim3 b256(256);
    dim3 tb(32, 8);

    // 1) split x
    split_planes2<<<(int)(ND / 512), b256>>>(x, xp0, xp1, (int)ND);

    // 2) fused Wq+Wk+Wv transpose (one launch, z=3)
    transpose_split3<<<dim3(DIM / 32, DIM / 32, 3), tb>>>(
        Wq, Wk, Wv, wqk0, wqk1, wqk0 + DD, wqk1 + DD, wv0, wv1, DIM, DIM);

    // 3) merged projections: [Q|K] (EPI=1) + V^T (EPI=2), 768 blocks
    proj_fused<<<768, b256, GEMM_SMEM>>>(
        xp0, xp1, wqk0, wqk1, qk0, qk1, wv0, wv1, vt);

    // 4) scores S = (1/32) Q K^T    (full 3-product accuracy)
    gemm_hmma<0, 3><<<dim3(SEQ / 128, SEQ / 128), b256, GEMM_SMEM>>>(
        qk0, qk1, qk0 + DIM, qk1 + DIM, S, nullptr, nullptr, nullptr,
        SEQ, DIM, 2 * DIM, 2 * DIM, SEQ, 0.03125f);

    // 5) softmax: unnormalized exp single plane + 1/sum
    softmax_exp1<<<SEQ, b256>>>(S, pp, inv);

    // 6) out = diag(inv) * P V   (single product: P 1-plane x V 1-plane)
    gemm_hmma<0, 1><<<dim3(DIM / 128, SEQ / 128), b256, GEMM_SMEM>>>(
        pp, nullptr, vt, nullptr, out, nullptr, nullptr, inv,
        DIM, SEQ, SEQ, SEQ, DIM, 1.0f);
}

// round 17
// speedup vs baseline: 5.1101x; 1.1334x over previous
#include <cuda_runtime.h>
#include <cuda_fp16.h>
#include <stdint.h>
#include <math.h>

#define SEQ 4096
#define DIM 1024

typedef __half h16;

// ---------------- static device scratch ----------------
__device__ h16  g_xp[2][SEQ * DIM];                 // x split planes [SEQ, DIM]
__device__ h16  g_Wqkt[2][2 * DIM * DIM];           // [Wq^T ; Wk^T] planes [2048, 1024]
__device__ h16  g_Wvt[2][DIM * DIM];                // Wv^T planes [1024, 1024]
__device__ h16  g_QKp[2][(size_t)SEQ * 2 * DIM];    // [Q | K] planes [SEQ, 2048]
__device__ h16  g_Vt[(size_t)DIM * SEQ];            // V^T single fp16 plane [DIM, SEQ]
__device__ float g_S[(size_t)SEQ * SEQ];
__device__ h16  g_Pp[(size_t)SEQ * SEQ];            // exp (unnormalized) single plane
__device__ float g_inv[SEQ];                        // per-row 1/sum

// ---------------- helpers ----------------
__device__ __forceinline__ uint32_t smem_u32(const void* p) {
    uint32_t a;
    asm("{ .reg .u64 t; cvta.to.shared.u64 t, %1; cvt.u32.u64 %0, t; }" : "=r"(a) : "l"(p));
    return a;
}
__device__ __forceinline__ uint32_t sw128(uint32_t o) { return o ^ ((o >> 3) & 0x70); }

__device__ __forceinline__ void cp_async16(uint32_t s, const void* g) {
    asm volatile("cp.async.cg.shared.global [%0], [%1], 16;" :: "r"(s), "l"(g));
}
#define CP_COMMIT() asm volatile("cp.async.commit_group;" ::: "memory")
#define CP_WAIT1()  asm volatile("cp.async.wait_group 1;" ::: "memory")

__device__ __forceinline__ void ldsm4(uint32_t& r0, uint32_t& r1, uint32_t& r2, uint32_t& r3, uint32_t a) {
    asm volatile("ldmatrix.sync.aligned.m8n8.x4.shared.b16 {%0,%1,%2,%3}, [%4];"
                 : "=r"(r0), "=r"(r1), "=r"(r2), "=r"(r3) : "r"(a));
}
__device__ __forceinline__ void mma16816(float* c, const uint32_t* a, const uint32_t* b) {
    asm volatile("mma.sync.aligned.m16n8k16.row.col.f32.f16.f16.f32 "
                 "{%0,%1,%2,%3}, {%4,%5,%6,%7}, {%8,%9}, {%0,%1,%2,%3};"
                 : "+f"(c[0]), "+f"(c[1]), "+f"(c[2]), "+f"(c[3])
                 : "r"(a[0]), "r"(a[1]), "r"(a[2]), "r"(a[3]), "r"(b[0]), "r"(b[1]));
}
__device__ __forceinline__ void split2(float v, h16& x0, h16& x1) {
    x0 = __float2half_rn(v);
    x1 = __float2half_rn(v - __half2float(x0));
}

// ---------------------------------------------------------------------------
// GEMM body:  C[M,N] = alpha * rowscale[m] * A[M,K] * B[N,K]^T  (K-major planes)
// NSEG=3: a0b0 + a0b1 + a1b0.  NSEG=2: a0b0 + a1b0.  NSEG=1: a0b0 only.
// CTA tile 128x128, BK=64, 8 warps (2x4 of 64x32), 3-stage cp.async pipeline
// (3 x 32KB smem -> 2 CTAs/SM, 16 warps/SM for latency hiding).
// EPI=0: fp32 C. EPI=1: 2 fp16 split planes. EPI=2: single fp16 plane.
// ---------------------------------------------------------------------------
template <int EPI, int NSEG>
__device__ __forceinline__ void gemm_body(
    int bx, int by, char* sm,
    const h16* __restrict__ a0, const h16* __restrict__ a1,
    const h16* __restrict__ b0, const h16* __restrict__ b1,
    float* __restrict__ C, h16* __restrict__ c0, h16* __restrict__ c1,
    const float* __restrict__ rowscale,
    int N, int Kd, int lda, int ldb, int ldc, float alpha)
{
    const uint32_t smu = smem_u32(sm);
    const int tid = threadIdx.x;
    const int wid = tid >> 5, lane = tid & 31;
    const int wm = wid >> 2, wn = wid & 3;            // 2x4 warp grid, 64x32 tiles
    const int row0 = by * 128, col0 = bx * 128;

    const h16* segA[3];
    const h16* segB[3];
    if (NSEG == 3) {
        segA[0] = a0; segA[1] = a0; segA[2] = a1;
        segB[0] = b0; segB[1] = b1; segB[2] = b0;
    } else if (NSEG == 2) {
        segA[0] = a0; segA[1] = a1; segA[2] = a1;
        segB[0] = b0; segB[1] = b0; segB[2] = b0;
    } else {
        segA[0] = a0; segA[1] = a0; segA[2] = a0;
        segB[0] = b0; segB[1] = b0; segB[2] = b0;
    }
    const int cpk = Kd >> 6;
    const int nc = NSEG * cpk;

    const int gr = tid >> 3;       // 0..31 base row
    const int gc = tid & 7;        // 16B granule in 128B row

    float acc[4][4][4];
#pragma unroll
    for (int i = 0; i < 4; i++)
#pragma unroll
        for (int j = 0; j < 4; j++)
#pragma unroll
            for (int q = 0; q < 4; q++) acc[i][j][q] = 0.0f;

    // fragment smem base offsets (lane-dependent only)
    const int arr = wm * 64 + (lane & 15);
    const uint32_t abase_lane = (uint32_t)(arr * 128 + ((lane >> 4) << 4));
    const int bnn = wn * 32 + ((lane >> 4) << 3) + (lane & 7);
    const uint32_t bbase_lane = (uint32_t)(bnn * 128 + (((lane >> 3) & 1) << 4));

    auto load_chunk = [&](int c, int b) {
        const int seg = c / cpk;
        const int kc = (c - seg * cpk) << 6;
        const h16* Ag = segA[seg];
        const h16* Bg = segB[seg];
        const uint32_t ab = smu + (uint32_t)b * 32768u;     // 32KB stage
        const uint32_t bb = ab + 16384u;                    // A:16KB, B:16KB
#pragma unroll
        for (int q = 0; q < 4; q++) {                       // A: 128 rows
            const int r = gr + q * 32;
            const uint32_t off = sw128((uint32_t)(r * 128 + gc * 16));
            cp_async16(ab + off, Ag + (size_t)(row0 + r) * lda + kc + gc * 8);
        }
#pragma unroll
        for (int q = 0; q < 4; q++) {                       // B: 128 rows
            const int r = gr + q * 32;
            const uint32_t off = sw128((uint32_t)(r * 128 + gc * 16));
            cp_async16(bb + off, Bg + (size_t)(col0 + r) * ldb + kc + gc * 8);
        }
        CP_COMMIT();
    };

    load_chunk(0, 0);
    load_chunk(1, 1);

    int stage = 0;
    for (int c = 0; c < nc; c++) {
        CP_WAIT1();            // chunk c resident
        __syncthreads();       // chunk c-1 consumers done -> its stage is free

        const uint32_t ab = smu + (uint32_t)stage * 32768u;
        const uint32_t bb = ab + 16384u;

        // issue next chunk's cp.async (into the stage freed by iter c-1)
        if (c + 2 < nc) {
            int s2 = stage + 2; if (s2 >= 3) s2 -= 3;
            load_chunk(c + 2, s2);
        } else {
            CP_COMMIT();
        }

#pragma unroll
        for (int ks = 0; ks < 4; ks++) {
            uint32_t af[4][4];
            uint32_t bf[4][2];
#pragma unroll
            for (int mt = 0; mt < 4; mt++) {
                const uint32_t off = sw128(abase_lane + (uint32_t)(mt * 16 * 128 + ks * 32));
                ldsm4(af[mt][0], af[mt][1], af[mt][2], af[mt][3], ab + off);
            }
#pragma unroll
            for (int nt2 = 0; nt2 < 2; nt2++) {
                const uint32_t off = sw128(bbase_lane + (uint32_t)(nt2 * 16 * 128 + ks * 32));
                uint32_t r0, r1, r2, r3;
                ldsm4(r0, r1, r2, r3, bb + off);
                bf[nt2 * 2][0] = r0;     bf[nt2 * 2][1] = r1;
                bf[nt2 * 2 + 1][0] = r2; bf[nt2 * 2 + 1][1] = r3;
            }
#pragma unroll
            for (int mt = 0; mt < 4; mt++)
#pragma unroll
                for (int nt = 0; nt < 4; nt++)
                    mma16816(acc[mt][nt], af[mt], bf[nt]);
        }

        if (++stage == 3) stage = 0;
    }

    // ---- epilogue ----
    const int gid = lane >> 2, tig = lane & 3;
#pragma unroll
    for (int mt = 0; mt < 4; mt++) {
        const int r_ = row0 + wm * 64 + mt * 16 + gid;
        const float rs0 = alpha * (rowscale ? rowscale[r_] : 1.0f);
        const float rs1 = alpha * (rowscale ? rowscale[r_ + 8] : 1.0f);
#pragma unroll
        for (int nt = 0; nt < 4; nt++) {
            const int cc = col0 + wn * 32 + nt * 8 + tig * 2;
            const float v0 = rs0 * acc[mt][nt][0];
            const float v1 = rs0 * acc[mt][nt][1];
            const float v2 = rs1 * acc[mt][nt][2];
            const float v3 = rs1 * acc[mt][nt][3];
            if (EPI == 0) {
                *reinterpret_cast<float2*>(&C[(size_t)r_ * ldc + cc]) = make_float2(v0, v1);
                *reinterpret_cast<float2*>(&C[(size_t)(r_ + 8) * ldc + cc]) = make_float2(v2, v3);
            } else if (EPI == 1) {
                h16 p0, p1, q0, q1;
                split2(v0, p0, p1); split2(v1, q0, q1);
                __half2 lo0; lo0.x = p0; lo0.y = q0;
                __half2 lo1; lo1.x = p1; lo1.y = q1;
                *reinterpret_cast<__half2*>(c0 + (size_t)r_ * ldc + cc) = lo0;
                *reinterpret_cast<__half2*>(c1 + (size_t)r_ * ldc + cc) = lo1;
                split2(v2, p0, p1); split2(v3, q0, q1);
                __half2 hi0; hi0.x = p0; hi0.y = q0;
                __half2 hi1; hi1.x = p1; hi1.y = q1;
                *reinterpret_cast<__half2*>(c0 + (size_t)(r_ + 8) * ldc + cc) = hi0;
                *reinterpret_cast<__half2*>(c1 + (size_t)(r_ + 8) * ldc + cc) = hi1;
            } else {
                __half2 lo; lo.x = __float2half_rn(v0); lo.y = __float2half_rn(v1);
                __half2 hi; hi.x = __float2half_rn(v2); hi.y = __float2half_rn(v3);
                *reinterpret_cast<__half2*>(c0 + (size_t)r_ * ldc + cc) = lo;
                *reinterpret_cast<__half2*>(c0 + (size_t)(r_ + 8) * ldc + cc) = hi;
            }
        }
    }
}

template <int EPI, int NSEG>
__global__ __launch_bounds__(256, 2) void gemm_hmma(
    const h16* __restrict__ a0, const h16* __restrict__ a1,
    const h16* __restrict__ b0, const h16* __restrict__ b1,
    float* __restrict__ C, h16* __restrict__ c0, h16* __restrict__ c1,
    const float* __restrict__ rowscale,
    int N, int Kd, int lda, int ldb, int ldc, float alpha)
{
    extern __shared__ char sm[];
    gemm_body<EPI, NSEG>(blockIdx.x, blockIdx.y, sm, a0, a1, b0, b1,
                         C, c0, c1, rowscale, N, Kd, lda, ldb, ldc, alpha);
}

// Merged projections: blocks [0,512) do fused [Q|K] (EPI=1, NSEG=3),
// [512,768) do V^T (EPI=2, NSEG=1 — single product, error below V quant floor).
__global__ __launch_bounds__(256, 2) void proj_fused(
    const h16* __restrict__ xp0, const h16* __restrict__ xp1,
    const h16* __restrict__ wqk0, const h16* __restrict__ wqk1,
    h16* __restrict__ qk0, h16* __restrict__ qk1,
    const h16* __restrict__ wv0, const h16* __restrict__ wv1,
    h16* __restrict__ vt)
{
    extern __shared__ char sm[];
    const int id = blockIdx.x;
    if (id < 512) {
        gemm_body<1, 3>(id & 15, id >> 4, sm, xp0, xp1, wqk0, wqk1,
                        nullptr, qk0, qk1, nullptr,
                        2 * DIM, DIM, DIM, DIM, 2 * DIM, 1.0f);
    } else {
        const int j = id - 512;
        gemm_body<2, 1>(j & 31, j >> 5, sm, wv0, nullptr, xp0, nullptr,
                        nullptr, vt, nullptr, nullptr,
                        SEQ, DIM, DIM, DIM, SEQ, 1.0f);
    }
}

#define GEMM_SMEM 98304

// ---------------------------------------------------------------------------
__global__ __launch_bounds__(256) void split_planes2(
    const float* __restrict__ src, h16* __restrict__ d0, h16* __restrict__ d1, int n)
{
    int i = (blockIdx.x * 256 + threadIdx.x) * 2;
    if (i < n) {
        float2 v = *reinterpret_cast<const float2*>(src + i);
        h16 a0, a1, b0, b1;
        split2(v.x, a0, a1); split2(v.y, b0, b1);
        __half2 p0; p0.x = a0; p0.y = b0;
        __half2 p1; p1.x = a1; p1.y = b1;
        *reinterpret_cast<__half2*>(d0 + i) = p0;
        *reinterpret_cast<__half2*>(d1 + i) = p1;
    }
}

// fp32 [R,C] -> transposed 2 fp16 planes [C,R]; blockIdx.z selects source
__global__ __launch_bounds__(256) void transpose_split3(
    const float* __restrict__ srcA, const float* __restrict__ srcB,
    const float* __restrict__ srcC,
    h16* __restrict__ dA0, h16* __restrict__ dA1,
    h16* __restrict__ dB0, h16* __restrict__ dB1,
    h16* __restrict__ dC0, h16* __restrict__ dC1, int R, int C)
{
    __shared__ float t[32][33];
    const float* src = (blockIdx.z == 0) ? srcA : (blockIdx.z == 1) ? srcB : srcC;
    h16* e0 = (blockIdx.z == 0) ? dA0 : (blockIdx.z == 1) ? dB0 : dC0;
    h16* e1 = (blockIdx.z == 0) ? dA1 : (blockIdx.z == 1) ? dB1 : dC1;
    const int tx = threadIdx.x, ty = threadIdx.y;
    const int r0 = blockIdx.y * 32, c0 = blockIdx.x * 32;
#pragma unroll
    for (int j = 0; j < 32; j += 8)
        t[ty + j][tx] = src[(size_t)(r0 + ty + j) * C + c0 + tx];
    __syncthreads();
#pragma unroll
    for (int j = 0; j < 32; j += 8) {
        float v = t[tx][ty + j];
        h16 h0, h1;
        split2(v, h0, h1);
        size_t o = (size_t)(c0 + ty + j) * R + r0 + tx;
        e0[o] = h0; e1[o] = h1;
    }
}

// ---------------------------------------------------------------------------
// Row softmax (unnormalized): P = exp(s - rowmax) as ONE fp16 plane,
// inv[row] = 1/sum. Normalization folded into PV epilogue. Fast __expf.
// ---------------------------------------------------------------------------
__global__ __launch_bounds__(256) void softmax_exp1(
    const float* __restrict__ S, h16* __restrict__ P0, float* __restrict__ inv)
{
    const int row = blockIdx.x;
    const float* p = S + (size_t)row * SEQ;
    const int tid = threadIdx.x;
    __shared__ float red[256];

    float mx = -INFINITY;
    for (int i = tid * 4; i < SEQ; i += 1024) {
        float4 v = *reinterpret_cast<const float4*>(p + i);
        mx = fmaxf(mx, fmaxf(fmaxf(v.x, v.y), fmaxf(v.z, v.w)));
    }
    red[tid] = mx;
    __syncthreads();
#pragma unroll
    for (int s = 128; s > 0; s >>= 1) {
        if (tid < s) red[tid] = fmaxf(red[tid], red[tid + s]);
        __syncthreads();
    }
    mx = red[0];
    __syncthreads();

    const size_t base = (size_t)row * SEQ;
    float sum = 0.0f;
    for (int i = tid * 4; i < SEQ; i += 1024) {
        float4 v = *reinterpret_cast<const float4*>(p + i);
        float e0 = __expf(v.x - mx);
        float e1 = __expf(v.y - mx);
        float e2 = __expf(v.z - mx);
        float e3 = __expf(v.w - mx);
        sum += (e0 + e1) + (e2 + e3);
        __half2 q0; q0.x = __float2half_rn(e0); q0.y = __float2half_rn(e1);
        __half2 q1; q1.x = __float2half_rn(e2); q1.y = __float2half_rn(e3);
        *reinterpret_cast<__half2*>(P0 + base + i) = q0;
        *reinterpret_cast<__half2*>(P0 + base + i + 2) = q1;
    }
    red[tid] = sum;
    __syncthreads();
#pragma unroll
    for (int s = 128; s > 0; s >>= 1) {
        if (tid < s) red[tid] += red[tid + s];
        __syncthreads();
    }
    if (tid == 0) inv[row] = 1.0f / red[0];
}

// ---------------------------------------------------------------------------
extern "C" void kernel_launch(void* const* d_in, const int* in_sizes, int n_in,
                              void* d_out, int out_size)
{
    const float* x  = (const float*)d_in[0];
    const float* Wq = (const float*)d_in[1];
    const float* Wk = (const float*)d_in[2];
    const float* Wv = (const float*)d_in[3];
    float* out = (float*)d_out;

    h16 *xp, *wqkt, *wvt, *qkp, *vt, *pp;
    float *S, *inv;
    cudaGetSymbolAddress((void**)&xp,   g_xp);
    cudaGetSymbolAddress((void**)&wqkt, g_Wqkt);
    cudaGetSymbolAddress((void**)&wvt,  g_Wvt);
    cudaGetSymbolAddress((void**)&qkp,  g_QKp);
    cudaGetSymbolAddress((void**)&vt,   g_Vt);
    cudaGetSymbolAddress((void**)&S,    g_S);
    cudaGetSymbolAddress((void**)&pp,   g_Pp);
    cudaGetSymbolAddress((void**)&inv,  g_inv);

    const size_t ND = (size_t)SEQ * DIM;      // 4M
    const size_t DD = (size_t)DIM * DIM;      // 1M
    const size_t N2 = (size_t)SEQ * 2 * DIM;  // 8M

    h16 *xp0 = xp, *xp1 = xp + ND;
    h16 *wqk0 = wqkt, *wqk1 = wqkt + 2 * DD;
    h16 *wv0 = wvt, *wv1 = wvt + DD;
    h16 *qk0 = qkp, *qk1 = qkp + N2;

    cudaFuncSetAttribute((const void*)gemm_hmma<0, 3>, cudaFuncAttributeMaxDynamicSharedMemorySize, GEMM_SMEM);
    cudaFuncSetAttribute((const void*)gemm_hmma<0, 1>, cudaFuncAttributeMaxDynamicSharedMemorySize, GEMM_SMEM);
    cudaFuncSetAttribute((const void*)proj_fused, cudaFuncAttributeMaxDynamicSharedMemorySize, GEMM_SMEM);

    dim3 b256(256);
    dim3 tb(32, 8);

    // 1) split x
    split_planes2<<<(int)(ND / 512), b256>>>(x, xp0, xp1, (int)ND);

    // 2) fused Wq+Wk+Wv transpose (one launch, z=3)
    transpose_split3<<<dim3(DIM / 32, DIM / 32, 3), tb>>>(
        Wq, Wk, Wv, wqk0, wqk1, wqk0 + DD, wqk1 + DD, wv0, wv1, DIM, DIM);

    // 3) merged projections: [Q|K] (NSEG=3) + V^T (NSEG=1), 768 blocks
    proj_fused<<<768, b256, GEMM_SMEM>>>(
        xp0, xp1, wqk0, wqk1, qk0, qk1, wv0, wv1, vt);

    // 4) scores S = (1/32) Q K^T    (full 3-product accuracy)
    gemm_hmma<0, 3><<<dim3(SEQ / 128, SEQ / 128), b256, GEMM_SMEM>>>(
        qk0, qk1, qk0 + DIM, qk1 + DIM, S, nullptr, nullptr, nullptr,
        SEQ, DIM, 2 * DIM, 2 * DIM, SEQ, 0.03125f);

    // 5) softmax: unnormalized exp single plane + 1/sum
    softmax_exp1<<<SEQ, b256>>>(S, pp, inv);

    // 6) out = diag(inv) * P V   (single product: P 1-plane x V 1-plane)
    gemm_hmma<0, 1><<<dim3(DIM / 128, SEQ / 128), b256, GEMM_SMEM>>>(
        pp, nullptr, vt, nullptr, out, nullptr, nullptr, inv,
        DIM, SEQ, SEQ, SEQ, DIM, 1.0f);
}